// round 12
// baseline (speedup 1.0000x reference)
#include <cuda_runtime.h>
#include <cuda_fp16.h>
#include <cstdint>

// ---------------- problem constants ----------------
#define HID 64
#define INDIM 4800
#define DEPTH 14
#define NNODES 16383
#define NGEMM 256
#define NLEAF 8192

// ---------------- device scratch ----------------
__device__ float g_Wx[NNODES * NGEMM];
__device__ __half g_Bh[NGEMM * INDIM];
__device__ float g_h[NNODES * HID];
__device__ float g_c[NNODES * HID];
__device__ float g_Uit[HID * HID];
__device__ float g_Uft[HID * HID];
__device__ float g_Uot[HID * HID];
__device__ float g_Uut[HID * HID];
__device__ float g_convWt[2 * HID * HID];
__device__ float g_v[3 * HID];
__device__ unsigned g_bar[32];

// ---------------- helpers ----------------
__device__ __forceinline__ float sigmoidf_(float x) { return 1.f / (1.f + __expf(-x)); }

__device__ __forceinline__ void mma_f16(float* d, const unsigned* a, const unsigned* b) {
    asm volatile(
        "mma.sync.aligned.m16n8k16.row.col.f32.f16.f16.f32 "
        "{%0,%1,%2,%3},{%4,%5,%6,%7},{%8,%9},{%0,%1,%2,%3};"
        : "+f"(d[0]), "+f"(d[1]), "+f"(d[2]), "+f"(d[3])
        : "r"(a[0]), "r"(a[1]), "r"(a[2]), "r"(a[3]), "r"(b[0]), "r"(b[1]));
}
__device__ __forceinline__ void ldsm_x4(unsigned& r0, unsigned& r1, unsigned& r2, unsigned& r3,
                                        unsigned addr) {
    asm volatile("ldmatrix.sync.aligned.m8n8.x4.shared.b16 {%0,%1,%2,%3}, [%4];"
                 : "=r"(r0), "=r"(r1), "=r"(r2), "=r"(r3) : "r"(addr));
}
__device__ __forceinline__ void cp_async16h(__half* smem_dst, const __half* gsrc) {
    unsigned sa = (unsigned)__cvta_generic_to_shared(smem_dst);
    asm volatile("cp.async.cg.shared.global [%0], [%1], 16;\n" :: "r"(sa), "l"(gsrc));
}
__device__ __forceinline__ void cp_commit() { asm volatile("cp.async.commit_group;\n" ::: "memory"); }

// ---------------- geometry ----------------
#define TGRID 148
#define THREADS 1024
#define TWARPS 32
#define TW (TGRID * TWARPS)

// GEMM: 128x256 tile, fp16, BK=32, 32 warps (8m x 4n), warp tile 16x64
#define GBLOCKS 128
#define BM 128
#define BN 256
#define BK 32
#define NK (INDIM / BK)        // 150
#define PADH 40
#define A_STH (BM * PADH)      // 5120 halves / stage (x2)
#define B_STH (BN * PADH)      // 10240 halves / stage (x4)
#define B_BASEH (2 * A_STH)
// GEMM smem bytes = (2*5120 + 4*10240)*2 = 102400

// tree smem layout (floats)
#define TS_UF 0
#define TS_UI 4096
#define TS_UO 8192
#define TS_UU 12288
#define TS_CV 16384
#define TS_WB 24576
#define SMEM_FLOATS (TS_WB + TWARPS * 640)     // 45056
#define SMEM_BYTES (SMEM_FLOATS * 4)           // 180224 (>= gemm 102400)

__device__ __forceinline__ void gridbar(int i) {
    __syncthreads();
    if (threadIdx.x == 0) {
        __threadfence();
        unsigned prev = atomicAdd(&g_bar[i], 1u);
        if (prev + 1u < (unsigned)TGRID) {
            while (*(volatile unsigned*)&g_bar[i] < (unsigned)TGRID) { __nanosleep(64); }
        }
        __threadfence();
    }
    __syncthreads();
}

// ---------------- one node-pair on one warp (weights in smem) ----------------
__device__ __forceinline__ void node_pair(int nd0, int nd1, bool two, int lane,
                                          const float* sUi, const float* sUf,
                                          const float* sUo, const float* sUu,
                                          const float* sCv, float* shw, float* scw,
                                          float* saw, float cb0, float cb1,
                                          float* __restrict__ out)
{
    ((float4*)shw)[lane]         = ((const float4*)(g_h + (size_t)(2 * nd0 + 1) * HID))[lane];
    ((float4*)(shw + 128))[lane] = ((const float4*)(g_h + (size_t)(2 * nd1 + 1) * HID))[lane];
    ((float4*)scw)[lane]         = ((const float4*)(g_c + (size_t)(2 * nd0 + 1) * HID))[lane];
    ((float4*)(scw + 128))[lane] = ((const float4*)(g_c + (size_t)(2 * nd1 + 1) * HID))[lane];
    const float* wx0 = g_Wx + (size_t)nd0 * NGEMM;
    const float* wx1 = g_Wx + (size_t)nd1 * NGEMM;
    float xf00 = wx0[64 + lane],  xf01 = wx0[96 + lane];
    float xf10 = wx1[64 + lane],  xf11 = wx1[96 + lane];
    __syncwarp();

    float a00 = cb0, a01 = cb1, a10 = cb0, a11 = cb1;
#pragma unroll 4
    for (int h = 0; h < 128; ++h) {
        float w0 = sCv[h * 64 + lane], w1 = sCv[h * 64 + lane + 32];
        float s0 = shw[h], s1 = shw[128 + h];
        a00 += s0 * w0; a01 += s0 * w1; a10 += s1 * w0; a11 += s1 * w1;
    }
    saw[lane] = a00; saw[lane + 32] = a01;
    saw[64 + lane] = a10; saw[96 + lane] = a11;

    float fl00 = xf00, fl01 = xf01, fl10 = xf10, fl11 = xf11;
    float fr00 = xf00, fr01 = xf01, fr10 = xf10, fr11 = xf11;
#pragma unroll 4
    for (int h = 0; h < 64; ++h) {
        float w0 = sUf[h * 64 + lane], w1 = sUf[h * 64 + lane + 32];
        float l0 = shw[h], r0 = shw[64 + h];
        float l1 = shw[128 + h], r1 = shw[192 + h];
        fl00 += l0 * w0; fl01 += l0 * w1; fl10 += l1 * w0; fl11 += l1 * w1;
        fr00 += r0 * w0; fr01 += r0 * w1; fr10 += r1 * w0; fr11 += r1 * w1;
    }
    float sf00 = sigmoidf_(fl00) * scw[lane]       + sigmoidf_(fr00) * scw[64 + lane];
    float sf01 = sigmoidf_(fl01) * scw[lane + 32]  + sigmoidf_(fr01) * scw[96 + lane];
    float sf10 = sigmoidf_(fl10) * scw[128 + lane] + sigmoidf_(fr10) * scw[192 + lane];
    float sf11 = sigmoidf_(fl11) * scw[160 + lane] + sigmoidf_(fr11) * scw[224 + lane];
    __syncwarp();

    float zi00 = wx0[lane],       zi01 = wx0[lane + 32];
    float zi10 = wx1[lane],       zi11 = wx1[lane + 32];
    float zo00 = wx0[128 + lane], zo01 = wx0[160 + lane];
    float zo10 = wx1[128 + lane], zo11 = wx1[160 + lane];
    float zu00 = wx0[192 + lane], zu01 = wx0[224 + lane];
    float zu10 = wx1[192 + lane], zu11 = wx1[224 + lane];
#pragma unroll 2
    for (int h = 0; h < 64; ++h) {
        float wi0 = sUi[h * 64 + lane], wi1 = sUi[h * 64 + lane + 32];
        float wo0 = sUo[h * 64 + lane], wo1 = sUo[h * 64 + lane + 32];
        float wu0 = sUu[h * 64 + lane], wu1 = sUu[h * 64 + lane + 32];
        float q0 = saw[h], q1 = saw[64 + h];
        zi00 += q0 * wi0; zi01 += q0 * wi1; zi10 += q1 * wi0; zi11 += q1 * wi1;
        zo00 += q0 * wo0; zo01 += q0 * wo1; zo10 += q1 * wo0; zo11 += q1 * wo1;
        zu00 += q0 * wu0; zu01 += q0 * wu1; zu10 += q1 * wu0; zu11 += q1 * wu1;
    }
    float c0 = sf00 + sigmoidf_(zi00) * tanhf(zu00);
    float h0 = sigmoidf_(zo00) * tanhf(c0);
    g_c[(size_t)nd0 * HID + lane] = c0;
    g_h[(size_t)nd0 * HID + lane] = h0;
    float c1 = sf01 + sigmoidf_(zi01) * tanhf(zu01);
    float h1 = sigmoidf_(zo01) * tanhf(c1);
    g_c[(size_t)nd0 * HID + lane + 32] = c1;
    g_h[(size_t)nd0 * HID + lane + 32] = h1;
    if (nd0 == 0) {
        out[lane] = h0;  out[lane + 32] = h1;
        out[64 + lane] = c0; out[96 + lane] = c1;
    }
    if (two) {
        float c2 = sf10 + sigmoidf_(zi10) * tanhf(zu10);
        g_c[(size_t)nd1 * HID + lane] = c2;
        g_h[(size_t)nd1 * HID + lane] = sigmoidf_(zo10) * tanhf(c2);
        float c3 = sf11 + sigmoidf_(zi11) * tanhf(zu11);
        g_c[(size_t)nd1 * HID + lane + 32] = c3;
        g_h[(size_t)nd1 * HID + lane + 32] = sigmoidf_(zo11) * tanhf(c3);
    }
    __syncwarp();
}

// ---------------- the mega-kernel ----------------
__global__ void __launch_bounds__(THREADS, 1)
mega_kernel(const float* __restrict__ A,
            const float* __restrict__ Wx_w,
            const float* __restrict__ Wx_b,
            const float* __restrict__ U_i, const float* __restrict__ U_f,
            const float* __restrict__ U_o, const float* __restrict__ U_u,
            const float* __restrict__ convW, const float* __restrict__ conv_b,
            float* __restrict__ out)
{
    extern __shared__ float sm[];
    __half* smh = (__half*)sm;
    const int tid  = threadIdx.x;
    const int lane = tid & 31;
    const int warp = tid >> 5;
    const int t0 = blockIdx.x * THREADS + tid;
    const int nt = TGRID * THREADS;

    // ========== phase 0: prep ==========
    for (int i = t0; i < NGEMM * INDIM / 4; i += nt) {
        float4 v = ((const float4*)Wx_w)[i];
        __half2 h0 = __floats2half2_rn(v.x, v.y);
        __half2 h1 = __floats2half2_rn(v.z, v.w);
        uint2 pk;
        pk.x = *(unsigned*)&h0; pk.y = *(unsigned*)&h1;
        ((uint2*)g_Bh)[i] = pk;
    }
    for (int idx = t0; idx < HID * HID; idx += nt) {
        int o = idx >> 6, h = idx & 63;
        g_Uit[h * HID + o] = U_i[idx];
        g_Uft[h * HID + o] = U_f[idx];
        g_Uot[h * HID + o] = U_o[idx];
        g_Uut[h * HID + o] = U_u[idx];
    }
    for (int idx = t0; idx < 2 * HID * HID; idx += nt) {
        int o = idx >> 7, kh = idx & 127;
        g_convWt[kh * HID + o] = convW[idx];
    }
    if (t0 < HID) {
        float vi = 0.f, vo = 0.f, vu = 0.f;
        for (int h = 0; h < HID; ++h) {
            float b = conv_b[h];
            vi += b * U_i[t0 * HID + h];
            vo += b * U_o[t0 * HID + h];
            vu += b * U_u[t0 * HID + h];
        }
        g_v[t0] = vi; g_v[HID + t0] = vo; g_v[2 * HID + t0] = vu;
    }
    gridbar(0);

    // ========== phase 1: fp16 GEMM, 32 warps, warp tile 16x64 ==========
    if (blockIdx.x < GBLOCKS) {
        const int m0row = (warp >> 2) * 16;   // 8 m-warps of 16 rows
        const int n0 = (warp & 3) * 64;       // 4 n-warps of 64 cols
        const int bm = blockIdx.x * BM;
        const int arow = tid >> 3;            // 0..127
        const int aq   = tid & 7;             // 0..7 (4-float chunk)
        int agr = bm + arow; if (agr > NNODES - 1) agr = NNODES - 1;
        const float* agp = A + (size_t)agr * INDIM + aq * 4;

        const int rA = lane & 15;
        const int cA = (lane >> 4) * 8;
        const int rB = (lane & 7) + (lane >> 4) * 8;
        const int cB = ((lane >> 3) & 1) * 8;
        const unsigned sbase = (unsigned)__cvta_generic_to_shared(smh);
        const unsigned uA0 = ((m0row + rA) * PADH + cA) * 2;
        const unsigned uB0 = ((n0 + rB) * PADH + cB) * 2;

        float acc[8][4];
#pragma unroll
        for (int j = 0; j < 8; ++j)
#pragma unroll
            for (int k = 0; k < 4; ++k) acc[j][k] = 0.f;

        float ar[4];
        auto ldgA = [&](int t) {
            float4 u = *(const float4*)(agp + t * BK);
            ar[0] = u.x; ar[1] = u.y; ar[2] = u.z; ar[3] = u.w;
        };
        auto stsA = [&](int t) {
            __half2 p0 = __floats2half2_rn(ar[0], ar[1]);
            __half2 p1 = __floats2half2_rn(ar[2], ar[3]);
            uint2 pk;
            pk.x = *(unsigned*)&p0; pk.y = *(unsigned*)&p1;
            *(uint2*)(smh + (t & 1) * A_STH + arow * PADH + aq * 4) = pk;
        };
        auto issueB = [&](int t) {
            __half* stg = smh + B_BASEH + (t & 3) * B_STH;
            const int k0 = t * BK;
            int row = tid >> 2, c = tid & 3;          // 1024 threads -> 1024 chunks
            cp_async16h(stg + row * PADH + c * 8,
                        g_Bh + (size_t)row * INDIM + k0 + c * 8);
            cp_commit();
        };

        ldgA(0);
        issueB(0); issueB(1);

        for (int s = 0; s < NK; ++s) {
            stsA(s);
            if (s + 1 < NK) ldgA(s + 1);
            if (s + 2 < NK) issueB(s + 2); else cp_commit();
            asm volatile("cp.async.wait_group 2;" ::: "memory");
            __syncthreads();

            const unsigned stA = sbase + ((s & 1) * A_STH) * 2;
            const unsigned stB = sbase + (B_BASEH + (s & 3) * B_STH) * 2;

#pragma unroll
            for (int ks = 0; ks < 2; ++ks) {
                unsigned af[4];
                ldsm_x4(af[0], af[1], af[2], af[3], stA + uA0 + ks * 32);
                // first 32 n-cols
                {
                    unsigned bf[4][2];
                    ldsm_x4(bf[0][0], bf[0][1], bf[1][0], bf[1][1],
                            stB + uB0 + ks * 32);
                    ldsm_x4(bf[2][0], bf[2][1], bf[3][0], bf[3][1],
                            stB + uB0 + 16 * PADH * 2 + ks * 32);
#pragma unroll
                    for (int in = 0; in < 4; ++in)
                        mma_f16(acc[in], af, bf[in]);
                }
                // second 32 n-cols
                {
                    unsigned bf[4][2];
                    ldsm_x4(bf[0][0], bf[0][1], bf[1][0], bf[1][1],
                            stB + uB0 + 32 * PADH * 2 + ks * 32);
                    ldsm_x4(bf[2][0], bf[2][1], bf[3][0], bf[3][1],
                            stB + uB0 + 48 * PADH * 2 + ks * 32);
#pragma unroll
                    for (int in = 0; in < 4; ++in)
                        mma_f16(acc[4 + in], af, bf[in]);
                }
            }
        }

        const int gid = lane >> 2, tig = lane & 3;
#pragma unroll
        for (int in = 0; in < 8; ++in) {
            int rr = bm + m0row + gid;
            int cg = n0 + in * 8 + tig * 2;
            float b0 = Wx_b[cg], b1 = Wx_b[cg + 1];
            if (rr < NNODES) {
                float2 v = make_float2(acc[in][0] + b0, acc[in][1] + b1);
                *(float2*)(g_Wx + (size_t)rr * NGEMM + cg) = v;
            }
            int rr2 = rr + 8;
            if (rr2 < NNODES) {
                float2 v = make_float2(acc[in][2] + b0, acc[in][3] + b1);
                *(float2*)(g_Wx + (size_t)rr2 * NGEMM + cg) = v;
            }
        }
        __syncthreads();
    }

    // stage tree weights into smem
    for (int i = tid; i < 4096; i += THREADS) {
        sm[TS_UF + i] = g_Uft[i];
        sm[TS_UI + i] = g_Uit[i];
        sm[TS_UO + i] = g_Uot[i];
        sm[TS_UU + i] = g_Uut[i];
    }
    for (int i = tid; i < 8192; i += THREADS) sm[TS_CV + i] = g_convWt[i];
    gridbar(1);

    // ========== phase 2: leaves ==========
    for (int idx = t0; idx < NLEAF * HID; idx += nt) {
        int node = (NLEAF - 1) + (idx >> 6);
        int o = idx & 63;
        const float* wx = g_Wx + (size_t)node * NGEMM;
        float zi = wx[o]       + g_v[o];
        float zo = wx[128 + o] + g_v[64 + o];
        float zu = wx[192 + o] + g_v[128 + o];
        float c = sigmoidf_(zi) * tanhf(zu);
        g_c[(size_t)node * HID + o] = c;
        g_h[(size_t)node * HID + o] = sigmoidf_(zo) * tanhf(c);
    }
    int bi = 2;
    gridbar(bi++);

    // ========== phase 3: levels d = 12..5, grid-wide ==========
    const int gw = blockIdx.x * TWARPS + warp;
    float* shw = sm + TS_WB + warp * 640;
    float* scw = shw + 256;
    float* saw = shw + 512;
    const float cb0 = conv_b[lane], cb1 = conv_b[lane + 32];

    for (int d = DEPTH - 2; d >= 5; --d) {
        const int n = 1 << d, start = n - 1;
        for (int j = gw * 2; j < n; j += TW * 2) {
            const bool two = (j + 1 < n);
            node_pair(start + j, start + j + (two ? 1 : 0), two, lane,
                      sm + TS_UI, sm + TS_UF, sm + TS_UO, sm + TS_UU, sm + TS_CV,
                      shw, scw, saw, cb0, cb1, out);
        }
        gridbar(bi++);          // bi 3..10
    }

    // ========== phase 4: levels d = 4..0, block 0 only ==========
    __syncthreads();
    if (blockIdx.x != 0) {
        if (tid == 0) { __threadfence(); atomicAdd(&g_bar[bi], 1u); }
        return;
    }
    if (tid == 0) {
        __threadfence();
        atomicAdd(&g_bar[bi], 1u);
        while (*(volatile unsigned*)&g_bar[bi] < (unsigned)TGRID) { __nanosleep(64); }
        __threadfence();
    }
    __syncthreads();

    for (int d = 4; d >= 0; --d) {
        const int n = 1 << d, start = n - 1;
        for (int j = warp * 2; j < n; j += TWARPS * 2) {
            const bool two = (j + 1 < n);
            node_pair(start + j, start + j + (two ? 1 : 0), two, lane,
                      sm + TS_UI, sm + TS_UF, sm + TS_UO, sm + TS_UU, sm + TS_CV,
                      shw, scw, saw, cb0, cb1, out);
        }
        __syncthreads();
    }

    if (tid < 32) g_bar[tid] = 0;   // reset for graph replay
}

// ---------------- launch ----------------
extern "C" void kernel_launch(void* const* d_in, const int* in_sizes, int n_in,
                              void* d_out, int out_size)
{
    const float* inputs = (const float*)d_in[0];
    const float* Wx_w   = (const float*)d_in[1];
    const float* Wx_b   = (const float*)d_in[2];
    const float* U_i    = (const float*)d_in[3];
    const float* U_f    = (const float*)d_in[4];
    const float* U_o    = (const float*)d_in[5];
    const float* U_u    = (const float*)d_in[6];
    const float* convW  = (const float*)d_in[7];
    const float* conv_b = (const float*)d_in[8];
    float* out = (float*)d_out;

    cudaFuncSetAttribute(mega_kernel, cudaFuncAttributeMaxDynamicSharedMemorySize, SMEM_BYTES);
    mega_kernel<<<TGRID, THREADS, SMEM_BYTES>>>(inputs, Wx_w, Wx_b, U_i, U_f, U_o, U_u,
                                                convW, conv_b, out);
}

// round 13
// speedup vs baseline: 1.3288x; 1.3288x over previous
#include <cuda_runtime.h>
#include <cuda_fp16.h>
#include <cstdint>

// ---------------- problem constants ----------------
#define HID 64
#define INDIM 4800
#define DEPTH 14
#define NNODES 16383
#define NGEMM 256
#define NLEAF 8192

// ---------------- device scratch ----------------
__device__ float g_Wx[NNODES * NGEMM];
__device__ __half g_Bh[NGEMM * INDIM];     // fp16 copy of Wx_w
__device__ float g_h[NNODES * HID];
__device__ float g_c[NNODES * HID];
__device__ float g_Uit[HID * HID];
__device__ float g_Uft[HID * HID];
__device__ float g_Uot[HID * HID];
__device__ float g_Uut[HID * HID];
__device__ float g_convWt[2 * HID * HID];
__device__ float g_v[3 * HID];
__device__ unsigned g_bar[32];

// ---------------- helpers ----------------
__device__ __forceinline__ float sigmoidf_(float x) { return 1.f / (1.f + __expf(-x)); }

__device__ __forceinline__ void mma_f16(float* d, const unsigned* a, const unsigned* b) {
    asm volatile(
        "mma.sync.aligned.m16n8k16.row.col.f32.f16.f16.f32 "
        "{%0,%1,%2,%3},{%4,%5,%6,%7},{%8,%9},{%0,%1,%2,%3};"
        : "+f"(d[0]), "+f"(d[1]), "+f"(d[2]), "+f"(d[3])
        : "r"(a[0]), "r"(a[1]), "r"(a[2]), "r"(a[3]), "r"(b[0]), "r"(b[1]));
}
__device__ __forceinline__ void ldsm_x4(unsigned& r0, unsigned& r1, unsigned& r2, unsigned& r3,
                                        unsigned addr) {
    asm volatile("ldmatrix.sync.aligned.m8n8.x4.shared.b16 {%0,%1,%2,%3}, [%4];"
                 : "=r"(r0), "=r"(r1), "=r"(r2), "=r"(r3) : "r"(addr));
}
__device__ __forceinline__ void cp_async16h(__half* smem_dst, const __half* gsrc) {
    unsigned sa = (unsigned)__cvta_generic_to_shared(smem_dst);
    asm volatile("cp.async.cg.shared.global [%0], [%1], 16;\n" :: "r"(sa), "l"(gsrc));
}
__device__ __forceinline__ void cp_commit() { asm volatile("cp.async.commit_group;\n" ::: "memory"); }

// ---------------- geometry ----------------
#define TGRID 148
#define THREADS 512
#define TWARPS 16
#define TW (TGRID * TWARPS)

// GEMM: 128x256 tile, fp16, BK=32, A x2 stages, B x6 stages
#define GBLOCKS 128
#define BM 128
#define BN 256
#define BK 32
#define NK (INDIM / BK)        // 150
#define PADH 40
#define A_STH (BM * PADH)      // 5120 halves / stage (x2)
#define B_STH (BN * PADH)      // 10240 halves / stage (x6)
#define B_BASEH (2 * A_STH)
#define NBSTG 6
// GEMM smem bytes = (2*5120 + 6*10240)*2 = 143360

// tree smem layout (floats)
#define TS_UF 0
#define TS_UI 4096
#define TS_UO 8192
#define TS_UU 12288
#define TS_CV 16384
#define TS_WB 24576
#define TREE_BYTES ((TS_WB + TWARPS * 640) * 4)   // 139264
#define SMEM_BYTES 143360                          // max(gemm, tree)

__device__ __forceinline__ void gridbar(int i) {
    __syncthreads();
    if (threadIdx.x == 0) {
        __threadfence();
        unsigned prev = atomicAdd(&g_bar[i], 1u);
        if (prev + 1u < (unsigned)TGRID) {
            while (*(volatile unsigned*)&g_bar[i] < (unsigned)TGRID) { __nanosleep(64); }
        }
        __threadfence();
    }
    __syncthreads();
}

// ---------------- one node-pair on one warp (weights in smem) ----------------
__device__ __forceinline__ void node_pair(int nd0, int nd1, bool two, int lane,
                                          const float* sUi, const float* sUf,
                                          const float* sUo, const float* sUu,
                                          const float* sCv, float* shw, float* scw,
                                          float* saw, float cb0, float cb1,
                                          float* __restrict__ out)
{
    ((float4*)shw)[lane]         = ((const float4*)(g_h + (size_t)(2 * nd0 + 1) * HID))[lane];
    ((float4*)(shw + 128))[lane] = ((const float4*)(g_h + (size_t)(2 * nd1 + 1) * HID))[lane];
    ((float4*)scw)[lane]         = ((const float4*)(g_c + (size_t)(2 * nd0 + 1) * HID))[lane];
    ((float4*)(scw + 128))[lane] = ((const float4*)(g_c + (size_t)(2 * nd1 + 1) * HID))[lane];
    const float* wx0 = g_Wx + (size_t)nd0 * NGEMM;
    const float* wx1 = g_Wx + (size_t)nd1 * NGEMM;
    float xf00 = wx0[64 + lane],  xf01 = wx0[96 + lane];
    float xf10 = wx1[64 + lane],  xf11 = wx1[96 + lane];
    __syncwarp();

    float a00 = cb0, a01 = cb1, a10 = cb0, a11 = cb1;
#pragma unroll 4
    for (int h = 0; h < 128; ++h) {
        float w0 = sCv[h * 64 + lane], w1 = sCv[h * 64 + lane + 32];
        float s0 = shw[h], s1 = shw[128 + h];
        a00 += s0 * w0; a01 += s0 * w1; a10 += s1 * w0; a11 += s1 * w1;
    }
    saw[lane] = a00; saw[lane + 32] = a01;
    saw[64 + lane] = a10; saw[96 + lane] = a11;

    float fl00 = xf00, fl01 = xf01, fl10 = xf10, fl11 = xf11;
    float fr00 = xf00, fr01 = xf01, fr10 = xf10, fr11 = xf11;
#pragma unroll 4
    for (int h = 0; h < 64; ++h) {
        float w0 = sUf[h * 64 + lane], w1 = sUf[h * 64 + lane + 32];
        float l0 = shw[h], r0 = shw[64 + h];
        float l1 = shw[128 + h], r1 = shw[192 + h];
        fl00 += l0 * w0; fl01 += l0 * w1; fl10 += l1 * w0; fl11 += l1 * w1;
        fr00 += r0 * w0; fr01 += r0 * w1; fr10 += r1 * w0; fr11 += r1 * w1;
    }
    float sf00 = sigmoidf_(fl00) * scw[lane]       + sigmoidf_(fr00) * scw[64 + lane];
    float sf01 = sigmoidf_(fl01) * scw[lane + 32]  + sigmoidf_(fr01) * scw[96 + lane];
    float sf10 = sigmoidf_(fl10) * scw[128 + lane] + sigmoidf_(fr10) * scw[192 + lane];
    float sf11 = sigmoidf_(fl11) * scw[160 + lane] + sigmoidf_(fr11) * scw[224 + lane];
    __syncwarp();

    float zi00 = wx0[lane],       zi01 = wx0[lane + 32];
    float zi10 = wx1[lane],       zi11 = wx1[lane + 32];
    float zo00 = wx0[128 + lane], zo01 = wx0[160 + lane];
    float zo10 = wx1[128 + lane], zo11 = wx1[160 + lane];
    float zu00 = wx0[192 + lane], zu01 = wx0[224 + lane];
    float zu10 = wx1[192 + lane], zu11 = wx1[224 + lane];
#pragma unroll 2
    for (int h = 0; h < 64; ++h) {
        float wi0 = sUi[h * 64 + lane], wi1 = sUi[h * 64 + lane + 32];
        float wo0 = sUo[h * 64 + lane], wo1 = sUo[h * 64 + lane + 32];
        float wu0 = sUu[h * 64 + lane], wu1 = sUu[h * 64 + lane + 32];
        float q0 = saw[h], q1 = saw[64 + h];
        zi00 += q0 * wi0; zi01 += q0 * wi1; zi10 += q1 * wi0; zi11 += q1 * wi1;
        zo00 += q0 * wo0; zo01 += q0 * wo1; zo10 += q1 * wo0; zo11 += q1 * wo1;
        zu00 += q0 * wu0; zu01 += q0 * wu1; zu10 += q1 * wu0; zu11 += q1 * wu1;
    }
    float c0 = sf00 + sigmoidf_(zi00) * tanhf(zu00);
    float h0 = sigmoidf_(zo00) * tanhf(c0);
    g_c[(size_t)nd0 * HID + lane] = c0;
    g_h[(size_t)nd0 * HID + lane] = h0;
    float c1 = sf01 + sigmoidf_(zi01) * tanhf(zu01);
    float h1 = sigmoidf_(zo01) * tanhf(c1);
    g_c[(size_t)nd0 * HID + lane + 32] = c1;
    g_h[(size_t)nd0 * HID + lane + 32] = h1;
    if (nd0 == 0) {
        out[lane] = h0;  out[lane + 32] = h1;
        out[64 + lane] = c0; out[96 + lane] = c1;
    }
    if (two) {
        float c2 = sf10 + sigmoidf_(zi10) * tanhf(zu10);
        g_c[(size_t)nd1 * HID + lane] = c2;
        g_h[(size_t)nd1 * HID + lane] = sigmoidf_(zo10) * tanhf(c2);
        float c3 = sf11 + sigmoidf_(zi11) * tanhf(zu11);
        g_c[(size_t)nd1 * HID + lane + 32] = c3;
        g_h[(size_t)nd1 * HID + lane + 32] = sigmoidf_(zo11) * tanhf(c3);
    }
    __syncwarp();
}

// ---------------- the mega-kernel ----------------
__global__ void __launch_bounds__(THREADS, 1)
mega_kernel(const float* __restrict__ A,
            const float* __restrict__ Wx_w,
            const float* __restrict__ Wx_b,
            const float* __restrict__ U_i, const float* __restrict__ U_f,
            const float* __restrict__ U_o, const float* __restrict__ U_u,
            const float* __restrict__ convW, const float* __restrict__ conv_b,
            float* __restrict__ out)
{
    extern __shared__ float sm[];
    __half* smh = (__half*)sm;
    const int tid  = threadIdx.x;
    const int lane = tid & 31;
    const int warp = tid >> 5;
    const int t0 = blockIdx.x * THREADS + tid;
    const int nt = TGRID * THREADS;

    // ========== phase 0: prep ==========
    for (int i = t0; i < NGEMM * INDIM / 4; i += nt) {
        float4 v = ((const float4*)Wx_w)[i];
        __half2 h0 = __floats2half2_rn(v.x, v.y);
        __half2 h1 = __floats2half2_rn(v.z, v.w);
        uint2 pk;
        pk.x = *(unsigned*)&h0; pk.y = *(unsigned*)&h1;
        ((uint2*)g_Bh)[i] = pk;
    }
    for (int idx = t0; idx < HID * HID; idx += nt) {
        int o = idx >> 6, h = idx & 63;
        g_Uit[h * HID + o] = U_i[idx];
        g_Uft[h * HID + o] = U_f[idx];
        g_Uot[h * HID + o] = U_o[idx];
        g_Uut[h * HID + o] = U_u[idx];
    }
    for (int idx = t0; idx < 2 * HID * HID; idx += nt) {
        int o = idx >> 7, kh = idx & 127;
        g_convWt[kh * HID + o] = convW[idx];
    }
    if (t0 < HID) {
        float vi = 0.f, vo = 0.f, vu = 0.f;
        for (int h = 0; h < HID; ++h) {
            float b = conv_b[h];
            vi += b * U_i[t0 * HID + h];
            vo += b * U_o[t0 * HID + h];
            vu += b * U_u[t0 * HID + h];
        }
        g_v[t0] = vi; g_v[HID + t0] = vo; g_v[2 * HID + t0] = vu;
    }
    gridbar(0);

    // ========== phase 1: fp16 GEMM with ldmatrix, 6-deep B pipe ==========
    if (blockIdx.x < GBLOCKS) {
        const int m0 = (warp >> 2) * 32;
        const int n0 = (warp & 3) * 64;
        const int bm = blockIdx.x * BM;
        const int arow = tid >> 2;
        const int aq   = tid & 3;
        int agr = bm + arow; if (agr > NNODES - 1) agr = NNODES - 1;
        const float* agp = A + (size_t)agr * INDIM + aq * 8;

        const int rA = lane & 15;
        const int cA = (lane >> 4) * 8;
        const int rB = (lane & 7) + (lane >> 4) * 8;
        const int cB = ((lane >> 3) & 1) * 8;
        const unsigned sbase = (unsigned)__cvta_generic_to_shared(smh);
        const unsigned uA0 = ((m0 + rA) * PADH + cA) * 2;
        const unsigned uB0 = ((n0 + rB) * PADH + cB) * 2;

        float acc[2][8][4];
#pragma unroll
        for (int i = 0; i < 2; ++i)
#pragma unroll
            for (int j = 0; j < 8; ++j)
#pragma unroll
                for (int k = 0; k < 4; ++k) acc[i][j][k] = 0.f;

        float ar[8];
        auto ldgA = [&](int t) {
            const float4* p = (const float4*)(agp + t * BK);
            float4 u = p[0], v = p[1];
            ar[0] = u.x; ar[1] = u.y; ar[2] = u.z; ar[3] = u.w;
            ar[4] = v.x; ar[5] = v.y; ar[6] = v.z; ar[7] = v.w;
        };
        auto stsA = [&](int t) {
            __half2 p0 = __floats2half2_rn(ar[0], ar[1]);
            __half2 p1 = __floats2half2_rn(ar[2], ar[3]);
            __half2 p2 = __floats2half2_rn(ar[4], ar[5]);
            __half2 p3 = __floats2half2_rn(ar[6], ar[7]);
            uint4 pk;
            pk.x = *(unsigned*)&p0; pk.y = *(unsigned*)&p1;
            pk.z = *(unsigned*)&p2; pk.w = *(unsigned*)&p3;
            *(uint4*)(smh + (t & 1) * A_STH + arow * PADH + aq * 8) = pk;
        };
        auto issueB = [&](int t) {
            __half* stg = smh + B_BASEH + (t % NBSTG) * B_STH;
            const int k0 = t * BK;
#pragma unroll
            for (int j = 0; j < 2; ++j) {
                int idx = tid + j * THREADS;
                int row = idx >> 2, c = idx & 3;
                cp_async16h(stg + row * PADH + c * 8,
                            g_Bh + (size_t)row * INDIM + k0 + c * 8);
            }
            cp_commit();
        };

        ldgA(0);
        issueB(0); issueB(1); issueB(2); issueB(3); issueB(4);

        for (int s = 0; s < NK; ++s) {
            stsA(s);
            if (s + 1 < NK) ldgA(s + 1);
            if (s + 5 < NK) issueB(s + 5); else cp_commit();
            asm volatile("cp.async.wait_group 5;" ::: "memory");
            __syncthreads();

            const unsigned stA = sbase + ((s & 1) * A_STH) * 2;
            const unsigned stB = sbase + (B_BASEH + (s % NBSTG) * B_STH) * 2;

#pragma unroll
            for (int ks = 0; ks < 2; ++ks) {
                unsigned af[2][4], bf[8][2];
                ldsm_x4(af[0][0], af[0][1], af[0][2], af[0][3],
                        stA + uA0 + ks * 32);
                ldsm_x4(af[1][0], af[1][1], af[1][2], af[1][3],
                        stA + uA0 + 16 * PADH * 2 + ks * 32);
#pragma unroll
                for (int j = 0; j < 4; ++j)
                    ldsm_x4(bf[2 * j][0], bf[2 * j][1], bf[2 * j + 1][0], bf[2 * j + 1][1],
                            stB + uB0 + j * 16 * PADH * 2 + ks * 32);
#pragma unroll
                for (int im = 0; im < 2; ++im)
#pragma unroll
                    for (int in = 0; in < 8; ++in)
                        mma_f16(acc[im][in], af[im], bf[in]);
            }
        }

        const int gid = lane >> 2, tig = lane & 3;
#pragma unroll
        for (int im = 0; im < 2; ++im) {
#pragma unroll
            for (int in = 0; in < 8; ++in) {
                int rr = bm + m0 + im * 16 + gid;
                int cg = n0 + in * 8 + tig * 2;
                float b0 = Wx_b[cg], b1 = Wx_b[cg + 1];
                if (rr < NNODES) {
                    float2 v = make_float2(acc[im][in][0] + b0, acc[im][in][1] + b1);
                    *(float2*)(g_Wx + (size_t)rr * NGEMM + cg) = v;
                }
                int rr2 = rr + 8;
                if (rr2 < NNODES) {
                    float2 v = make_float2(acc[im][in][2] + b0, acc[im][in][3] + b1);
                    *(float2*)(g_Wx + (size_t)rr2 * NGEMM + cg) = v;
                }
            }
        }
        __syncthreads();
    }

    // stage tree weights into smem
    for (int i = tid; i < 4096; i += THREADS) {
        sm[TS_UF + i] = g_Uft[i];
        sm[TS_UI + i] = g_Uit[i];
        sm[TS_UO + i] = g_Uot[i];
        sm[TS_UU + i] = g_Uut[i];
    }
    for (int i = tid; i < 8192; i += THREADS) sm[TS_CV + i] = g_convWt[i];
    gridbar(1);

    // ========== phase 2: leaves ==========
    for (int idx = t0; idx < NLEAF * HID; idx += nt) {
        int node = (NLEAF - 1) + (idx >> 6);
        int o = idx & 63;
        const float* wx = g_Wx + (size_t)node * NGEMM;
        float zi = wx[o]       + g_v[o];
        float zo = wx[128 + o] + g_v[64 + o];
        float zu = wx[192 + o] + g_v[128 + o];
        float c = sigmoidf_(zi) * tanhf(zu);
        g_c[(size_t)node * HID + o] = c;
        g_h[(size_t)node * HID + o] = sigmoidf_(zo) * tanhf(c);
    }
    int bi = 2;
    gridbar(bi++);

    // ========== phase 3: levels d = 12..5, grid-wide ==========
    const int gw = blockIdx.x * TWARPS + warp;
    float* shw = sm + TS_WB + warp * 640;
    float* scw = shw + 256;
    float* saw = shw + 512;
    const float cb0 = conv_b[lane], cb1 = conv_b[lane + 32];

    for (int d = DEPTH - 2; d >= 5; --d) {
        const int n = 1 << d, start = n - 1;
        for (int j = gw * 2; j < n; j += TW * 2) {
            const bool two = (j + 1 < n);
            node_pair(start + j, start + j + (two ? 1 : 0), two, lane,
                      sm + TS_UI, sm + TS_UF, sm + TS_UO, sm + TS_UU, sm + TS_CV,
                      shw, scw, saw, cb0, cb1, out);
        }
        gridbar(bi++);
    }

    // ========== phase 4: levels d = 4..0, block 0 only ==========
    __syncthreads();
    if (blockIdx.x != 0) {
        if (tid == 0) { __threadfence(); atomicAdd(&g_bar[bi], 1u); }
        return;
    }
    if (tid == 0) {
        __threadfence();
        atomicAdd(&g_bar[bi], 1u);
        while (*(volatile unsigned*)&g_bar[bi] < (unsigned)TGRID) { __nanosleep(64); }
        __threadfence();
    }
    __syncthreads();

    for (int d = 4; d >= 0; --d) {
        const int n = 1 << d, start = n - 1;
        for (int j = warp * 2; j < n; j += TWARPS * 2) {
            const bool two = (j + 1 < n);
            node_pair(start + j, start + j + (two ? 1 : 0), two, lane,
                      sm + TS_UI, sm + TS_UF, sm + TS_UO, sm + TS_UU, sm + TS_CV,
                      shw, scw, saw, cb0, cb1, out);
        }
        __syncthreads();
    }

    if (tid < 32) g_bar[tid] = 0;   // reset for graph replay
}

// ---------------- launch ----------------
extern "C" void kernel_launch(void* const* d_in, const int* in_sizes, int n_in,
                              void* d_out, int out_size)
{
    const float* inputs = (const float*)d_in[0];
    const float* Wx_w   = (const float*)d_in[1];
    const float* Wx_b   = (const float*)d_in[2];
    const float* U_i    = (const float*)d_in[3];
    const float* U_f    = (const float*)d_in[4];
    const float* U_o    = (const float*)d_in[5];
    const float* U_u    = (const float*)d_in[6];
    const float* convW  = (const float*)d_in[7];
    const float* conv_b = (const float*)d_in[8];
    float* out = (float*)d_out;

    cudaFuncSetAttribute(mega_kernel, cudaFuncAttributeMaxDynamicSharedMemorySize, SMEM_BYTES);
    mega_kernel<<<TGRID, THREADS, SMEM_BYTES>>>(inputs, Wx_w, Wx_b, U_i, U_f, U_o, U_u,
                                                convW, conv_b, out);
}

// round 14
// speedup vs baseline: 1.3576x; 1.0217x over previous
#include <cuda_runtime.h>
#include <cuda_fp16.h>
#include <cstdint>

// ---------------- problem constants ----------------
#define HID 64
#define INDIM 4800
#define DEPTH 14
#define NNODES 16383
#define NGEMM 256
#define NLEAF 8192
#define FIRST_LEAF 8191

// ---------------- device scratch ----------------
__device__ float g_Wx[NNODES * NGEMM];
__device__ __half g_Bh[NGEMM * INDIM];     // fp16 copy of Wx_w
__device__ float g_h[NNODES * HID];
__device__ float g_c[NNODES * HID];
__device__ float g_Uit[HID * HID];
__device__ float g_Uft[HID * HID];
__device__ float g_Uot[HID * HID];
__device__ float g_Uut[HID * HID];
__device__ float g_convWt[2 * HID * HID];
__device__ float g_v[3 * HID];
__device__ unsigned g_bar[32];

// ---------------- helpers ----------------
__device__ __forceinline__ float sigmoidf_(float x) { return 1.f / (1.f + __expf(-x)); }

__device__ __forceinline__ void mma_f16(float* d, const unsigned* a, const unsigned* b) {
    asm volatile(
        "mma.sync.aligned.m16n8k16.row.col.f32.f16.f16.f32 "
        "{%0,%1,%2,%3},{%4,%5,%6,%7},{%8,%9},{%0,%1,%2,%3};"
        : "+f"(d[0]), "+f"(d[1]), "+f"(d[2]), "+f"(d[3])
        : "r"(a[0]), "r"(a[1]), "r"(a[2]), "r"(a[3]), "r"(b[0]), "r"(b[1]));
}
__device__ __forceinline__ void ldsm_x4(unsigned& r0, unsigned& r1, unsigned& r2, unsigned& r3,
                                        unsigned addr) {
    asm volatile("ldmatrix.sync.aligned.m8n8.x4.shared.b16 {%0,%1,%2,%3}, [%4];"
                 : "=r"(r0), "=r"(r1), "=r"(r2), "=r"(r3) : "r"(addr));
}
__device__ __forceinline__ void cp_async16h(__half* smem_dst, const __half* gsrc) {
    unsigned sa = (unsigned)__cvta_generic_to_shared(smem_dst);
    asm volatile("cp.async.cg.shared.global [%0], [%1], 16;\n" :: "r"(sa), "l"(gsrc));
}
__device__ __forceinline__ void cp_commit() { asm volatile("cp.async.commit_group;\n" ::: "memory"); }

// ---------------- geometry ----------------
#define TGRID 148
#define THREADS 512
#define TWARPS 16
#define TW (TGRID * TWARPS)

// GEMM: 128x256 tile, fp16, BK=32, A x2 stages, B x4 stages (r9 proven)
#define GBLOCKS 128
#define BM 128
#define BN 256
#define BK 32
#define NK (INDIM / BK)        // 150
#define PADH 40
#define A_STH (BM * PADH)      // 5120 halves / stage (x2)
#define B_STH (BN * PADH)      // 10240 halves / stage (x4)
#define B_BASEH (2 * A_STH)
// GEMM stages = (2*5120 + 4*10240)*2 = 102400 B; epilogue Wx buffer = 131072 B

// tree smem layout (floats)
#define TS_UF 0
#define TS_UI 4096
#define TS_UO 8192
#define TS_UU 12288
#define TS_CV 16384
#define TS_WB 24576
#define SMEM_FLOATS (TS_WB + TWARPS * 640)     // 34816
#define SMEM_BYTES (SMEM_FLOATS * 4)           // 139264 B (>= 131072 epilogue, >= 102400 stages)

__device__ __forceinline__ void gridbar(int i) {
    __syncthreads();
    if (threadIdx.x == 0) {
        __threadfence();
        unsigned prev = atomicAdd(&g_bar[i], 1u);
        if (prev + 1u < (unsigned)TGRID) {
            while (*(volatile unsigned*)&g_bar[i] < (unsigned)TGRID) { __nanosleep(64); }
        }
        __threadfence();
    }
    __syncthreads();
}

// ---------------- one node-pair on one warp (weights in smem) ----------------
__device__ __forceinline__ void node_pair(int nd0, int nd1, bool two, int lane,
                                          const float* sUi, const float* sUf,
                                          const float* sUo, const float* sUu,
                                          const float* sCv, float* shw, float* scw,
                                          float* saw, float cb0, float cb1,
                                          float* __restrict__ out)
{
    ((float4*)shw)[lane]         = ((const float4*)(g_h + (size_t)(2 * nd0 + 1) * HID))[lane];
    ((float4*)(shw + 128))[lane] = ((const float4*)(g_h + (size_t)(2 * nd1 + 1) * HID))[lane];
    ((float4*)scw)[lane]         = ((const float4*)(g_c + (size_t)(2 * nd0 + 1) * HID))[lane];
    ((float4*)(scw + 128))[lane] = ((const float4*)(g_c + (size_t)(2 * nd1 + 1) * HID))[lane];
    const float* wx0 = g_Wx + (size_t)nd0 * NGEMM;
    const float* wx1 = g_Wx + (size_t)nd1 * NGEMM;
    float xf00 = wx0[64 + lane],  xf01 = wx0[96 + lane];
    float xf10 = wx1[64 + lane],  xf11 = wx1[96 + lane];
    __syncwarp();

    float a00 = cb0, a01 = cb1, a10 = cb0, a11 = cb1;
#pragma unroll 4
    for (int h = 0; h < 128; ++h) {
        float w0 = sCv[h * 64 + lane], w1 = sCv[h * 64 + lane + 32];
        float s0 = shw[h], s1 = shw[128 + h];
        a00 += s0 * w0; a01 += s0 * w1; a10 += s1 * w0; a11 += s1 * w1;
    }
    saw[lane] = a00; saw[lane + 32] = a01;
    saw[64 + lane] = a10; saw[96 + lane] = a11;

    float fl00 = xf00, fl01 = xf01, fl10 = xf10, fl11 = xf11;
    float fr00 = xf00, fr01 = xf01, fr10 = xf10, fr11 = xf11;
#pragma unroll 4
    for (int h = 0; h < 64; ++h) {
        float w0 = sUf[h * 64 + lane], w1 = sUf[h * 64 + lane + 32];
        float l0 = shw[h], r0 = shw[64 + h];
        float l1 = shw[128 + h], r1 = shw[192 + h];
        fl00 += l0 * w0; fl01 += l0 * w1; fl10 += l1 * w0; fl11 += l1 * w1;
        fr00 += r0 * w0; fr01 += r0 * w1; fr10 += r1 * w0; fr11 += r1 * w1;
    }
    float sf00 = sigmoidf_(fl00) * scw[lane]       + sigmoidf_(fr00) * scw[64 + lane];
    float sf01 = sigmoidf_(fl01) * scw[lane + 32]  + sigmoidf_(fr01) * scw[96 + lane];
    float sf10 = sigmoidf_(fl10) * scw[128 + lane] + sigmoidf_(fr10) * scw[192 + lane];
    float sf11 = sigmoidf_(fl11) * scw[160 + lane] + sigmoidf_(fr11) * scw[224 + lane];
    __syncwarp();

    float zi00 = wx0[lane],       zi01 = wx0[lane + 32];
    float zi10 = wx1[lane],       zi11 = wx1[lane + 32];
    float zo00 = wx0[128 + lane], zo01 = wx0[160 + lane];
    float zo10 = wx1[128 + lane], zo11 = wx1[160 + lane];
    float zu00 = wx0[192 + lane], zu01 = wx0[224 + lane];
    float zu10 = wx1[192 + lane], zu11 = wx1[224 + lane];
#pragma unroll 2
    for (int h = 0; h < 64; ++h) {
        float wi0 = sUi[h * 64 + lane], wi1 = sUi[h * 64 + lane + 32];
        float wo0 = sUo[h * 64 + lane], wo1 = sUo[h * 64 + lane + 32];
        float wu0 = sUu[h * 64 + lane], wu1 = sUu[h * 64 + lane + 32];
        float q0 = saw[h], q1 = saw[64 + h];
        zi00 += q0 * wi0; zi01 += q0 * wi1; zi10 += q1 * wi0; zi11 += q1 * wi1;
        zo00 += q0 * wo0; zo01 += q0 * wo1; zo10 += q1 * wo0; zo11 += q1 * wo1;
        zu00 += q0 * wu0; zu01 += q0 * wu1; zu10 += q1 * wu0; zu11 += q1 * wu1;
    }
    float c0 = sf00 + sigmoidf_(zi00) * tanhf(zu00);
    float h0 = sigmoidf_(zo00) * tanhf(c0);
    g_c[(size_t)nd0 * HID + lane] = c0;
    g_h[(size_t)nd0 * HID + lane] = h0;
    float c1 = sf01 + sigmoidf_(zi01) * tanhf(zu01);
    float h1 = sigmoidf_(zo01) * tanhf(c1);
    g_c[(size_t)nd0 * HID + lane + 32] = c1;
    g_h[(size_t)nd0 * HID + lane + 32] = h1;
    if (nd0 == 0) {
        out[lane] = h0;  out[lane + 32] = h1;
        out[64 + lane] = c0; out[96 + lane] = c1;
    }
    if (two) {
        float c2 = sf10 + sigmoidf_(zi10) * tanhf(zu10);
        g_c[(size_t)nd1 * HID + lane] = c2;
        g_h[(size_t)nd1 * HID + lane] = sigmoidf_(zo10) * tanhf(c2);
        float c3 = sf11 + sigmoidf_(zi11) * tanhf(zu11);
        g_c[(size_t)nd1 * HID + lane + 32] = c3;
        g_h[(size_t)nd1 * HID + lane + 32] = sigmoidf_(zo11) * tanhf(c3);
    }
    __syncwarp();
}

// ---------------- the mega-kernel ----------------
__global__ void __launch_bounds__(THREADS, 1)
mega_kernel(const float* __restrict__ A,
            const float* __restrict__ Wx_w,
            const float* __restrict__ Wx_b,
            const float* __restrict__ U_i, const float* __restrict__ U_f,
            const float* __restrict__ U_o, const float* __restrict__ U_u,
            const float* __restrict__ convW, const float* __restrict__ conv_b,
            float* __restrict__ out)
{
    extern __shared__ float sm[];
    __half* smh = (__half*)sm;
    const int tid  = threadIdx.x;
    const int lane = tid & 31;
    const int warp = tid >> 5;
    const int t0 = blockIdx.x * THREADS + tid;
    const int nt = TGRID * THREADS;

    // ========== phase 0: prep ==========
    for (int i = t0; i < NGEMM * INDIM / 4; i += nt) {
        float4 v = ((const float4*)Wx_w)[i];
        __half2 h0 = __floats2half2_rn(v.x, v.y);
        __half2 h1 = __floats2half2_rn(v.z, v.w);
        uint2 pk;
        pk.x = *(unsigned*)&h0; pk.y = *(unsigned*)&h1;
        ((uint2*)g_Bh)[i] = pk;
    }
    for (int idx = t0; idx < HID * HID; idx += nt) {
        int o = idx >> 6, h = idx & 63;
        g_Uit[h * HID + o] = U_i[idx];
        g_Uft[h * HID + o] = U_f[idx];
        g_Uot[h * HID + o] = U_o[idx];
        g_Uut[h * HID + o] = U_u[idx];
    }
    for (int idx = t0; idx < 2 * HID * HID; idx += nt) {
        int o = idx >> 7, kh = idx & 127;
        g_convWt[kh * HID + o] = convW[idx];
    }
    if (t0 < HID) {
        float vi = 0.f, vo = 0.f, vu = 0.f;
        for (int h = 0; h < HID; ++h) {
            float b = conv_b[h];
            vi += b * U_i[t0 * HID + h];
            vo += b * U_o[t0 * HID + h];
            vu += b * U_u[t0 * HID + h];
        }
        g_v[t0] = vi; g_v[HID + t0] = vo; g_v[2 * HID + t0] = vu;
    }
    gridbar(0);

    // ========== phase 1: fp16 GEMM (r9) with fused leaf epilogue ==========
    if (blockIdx.x < GBLOCKS) {
        const int m0 = (warp >> 2) * 32;
        const int n0 = (warp & 3) * 64;
        const int bm = blockIdx.x * BM;
        const int arow = tid >> 2;
        const int aq   = tid & 3;
        int agr = bm + arow; if (agr > NNODES - 1) agr = NNODES - 1;
        const float* agp = A + (size_t)agr * INDIM + aq * 8;

        const int rA = lane & 15;
        const int cA = (lane >> 4) * 8;
        const int rB = (lane & 7) + (lane >> 4) * 8;
        const int cB = ((lane >> 3) & 1) * 8;
        const unsigned sbase = (unsigned)__cvta_generic_to_shared(smh);
        const unsigned uA0 = ((m0 + rA) * PADH + cA) * 2;
        const unsigned uB0 = ((n0 + rB) * PADH + cB) * 2;

        float acc[2][8][4];
#pragma unroll
        for (int i = 0; i < 2; ++i)
#pragma unroll
            for (int j = 0; j < 8; ++j)
#pragma unroll
                for (int k = 0; k < 4; ++k) acc[i][j][k] = 0.f;

        float ar[8];
        auto ldgA = [&](int t) {
            const float4* p = (const float4*)(agp + t * BK);
            float4 u = p[0], v = p[1];
            ar[0] = u.x; ar[1] = u.y; ar[2] = u.z; ar[3] = u.w;
            ar[4] = v.x; ar[5] = v.y; ar[6] = v.z; ar[7] = v.w;
        };
        auto stsA = [&](int t) {
            __half2 p0 = __floats2half2_rn(ar[0], ar[1]);
            __half2 p1 = __floats2half2_rn(ar[2], ar[3]);
            __half2 p2 = __floats2half2_rn(ar[4], ar[5]);
            __half2 p3 = __floats2half2_rn(ar[6], ar[7]);
            uint4 pk;
            pk.x = *(unsigned*)&p0; pk.y = *(unsigned*)&p1;
            pk.z = *(unsigned*)&p2; pk.w = *(unsigned*)&p3;
            *(uint4*)(smh + (t & 1) * A_STH + arow * PADH + aq * 8) = pk;
        };
        auto issueB = [&](int t) {
            __half* stg = smh + B_BASEH + (t & 3) * B_STH;
            const int k0 = t * BK;
#pragma unroll
            for (int j = 0; j < 2; ++j) {
                int idx = tid + j * THREADS;
                int row = idx >> 2, c = idx & 3;
                cp_async16h(stg + row * PADH + c * 8,
                            g_Bh + (size_t)row * INDIM + k0 + c * 8);
            }
            cp_commit();
        };

        ldgA(0);
        issueB(0); issueB(1);

        for (int s = 0; s < NK; ++s) {
            stsA(s);
            if (s + 1 < NK) ldgA(s + 1);
            if (s + 2 < NK) issueB(s + 2); else cp_commit();
            asm volatile("cp.async.wait_group 2;" ::: "memory");
            __syncthreads();

            const unsigned stA = sbase + ((s & 1) * A_STH) * 2;
            const unsigned stB = sbase + (B_BASEH + (s & 3) * B_STH) * 2;

#pragma unroll
            for (int ks = 0; ks < 2; ++ks) {
                unsigned af[2][4], bf[8][2];
                ldsm_x4(af[0][0], af[0][1], af[0][2], af[0][3],
                        stA + uA0 + ks * 32);
                ldsm_x4(af[1][0], af[1][1], af[1][2], af[1][3],
                        stA + uA0 + 16 * PADH * 2 + ks * 32);
#pragma unroll
                for (int j = 0; j < 4; ++j)
                    ldsm_x4(bf[2 * j][0], bf[2 * j][1], bf[2 * j + 1][0], bf[2 * j + 1][1],
                            stB + uB0 + j * 16 * PADH * 2 + ks * 32);
#pragma unroll
                for (int im = 0; im < 2; ++im)
#pragma unroll
                    for (int in = 0; in < 8; ++in)
                        mma_f16(acc[im][in], af[im], bf[in]);
            }
        }

        // ---- epilogue: acc+bias -> smem buffer [128][256], then per-row dispatch ----
        __syncthreads();                 // all warps done with stage smem
        float* swx = sm;                 // 128*256 floats = 131072 B
        const int gid = lane >> 2, tig = lane & 3;
#pragma unroll
        for (int im = 0; im < 2; ++im) {
#pragma unroll
            for (int in = 0; in < 8; ++in) {
                int r0 = m0 + im * 16 + gid;
                int cg = n0 + in * 8 + tig * 2;
                float b0 = Wx_b[cg], b1 = Wx_b[cg + 1];
                swx[r0 * 256 + cg]           = acc[im][in][0] + b0;
                swx[r0 * 256 + cg + 1]       = acc[im][in][1] + b1;
                swx[(r0 + 8) * 256 + cg]     = acc[im][in][2] + b0;
                swx[(r0 + 8) * 256 + cg + 1] = acc[im][in][3] + b1;
            }
        }
        __syncthreads();

#pragma unroll
        for (int k = 0; k < 16; ++k) {
            int idx = tid + k * THREADS;        // 0..8191
            int row = idx >> 6, o = idx & 63;
            int node = bm + row;
            if (node < FIRST_LEAF) {
                // internal node: store all four gates to g_Wx (coalesced per gate)
                float* dst = g_Wx + (size_t)node * NGEMM;
                const float* src = swx + row * 256;
                dst[o]       = src[o];
                dst[64 + o]  = src[64 + o];
                dst[128 + o] = src[128 + o];
                dst[192 + o] = src[192 + o];
            } else if (node < NNODES) {
                // leaf: compute h,c directly
                const float* src = swx + row * 256;
                float zi = src[o]       + g_v[o];
                float zo = src[128 + o] + g_v[64 + o];
                float zu = src[192 + o] + g_v[128 + o];
                float c = sigmoidf_(zi) * tanhf(zu);
                g_c[(size_t)node * HID + o] = c;
                g_h[(size_t)node * HID + o] = sigmoidf_(zo) * tanhf(c);
            }
        }
        __syncthreads();
    }

    // stage tree weights into smem
    for (int i = tid; i < 4096; i += THREADS) {
        sm[TS_UF + i] = g_Uft[i];
        sm[TS_UI + i] = g_Uit[i];
        sm[TS_UO + i] = g_Uot[i];
        sm[TS_UU + i] = g_Uut[i];
    }
    for (int i = tid; i < 8192; i += THREADS) sm[TS_CV + i] = g_convWt[i];
    int bi = 1;
    gridbar(bi++);

    // ========== phase 2: levels d = 12..5, grid-wide ==========
    const int gw = blockIdx.x * TWARPS + warp;
    float* shw = sm + TS_WB + warp * 640;
    float* scw = shw + 256;
    float* saw = shw + 512;
    const float cb0 = conv_b[lane], cb1 = conv_b[lane + 32];

    for (int d = DEPTH - 2; d >= 5; --d) {
        const int n = 1 << d, start = n - 1;
        for (int j = gw * 2; j < n; j += TW * 2) {
            const bool two = (j + 1 < n);
            node_pair(start + j, start + j + (two ? 1 : 0), two, lane,
                      sm + TS_UI, sm + TS_UF, sm + TS_UO, sm + TS_UU, sm + TS_CV,
                      shw, scw, saw, cb0, cb1, out);
        }
        gridbar(bi++);          // bi 2..9
    }

    // ========== phase 3: levels d = 4..0, block 0 only ==========
    __syncthreads();
    if (blockIdx.x != 0) {
        if (tid == 0) { __threadfence(); atomicAdd(&g_bar[bi], 1u); }
        return;
    }
    if (tid == 0) {
        __threadfence();
        atomicAdd(&g_bar[bi], 1u);
        while (*(volatile unsigned*)&g_bar[bi] < (unsigned)TGRID) { __nanosleep(64); }
        __threadfence();
    }
    __syncthreads();

    for (int d = 4; d >= 0; --d) {
        const int n = 1 << d, start = n - 1;
        for (int j = warp * 2; j < n; j += TWARPS * 2) {
            const bool two = (j + 1 < n);
            node_pair(start + j, start + j + (two ? 1 : 0), two, lane,
                      sm + TS_UI, sm + TS_UF, sm + TS_UO, sm + TS_UU, sm + TS_CV,
                      shw, scw, saw, cb0, cb1, out);
        }
        __syncthreads();
    }

    if (tid < 32) g_bar[tid] = 0;   // reset for graph replay
}

// ---------------- launch ----------------
extern "C" void kernel_launch(void* const* d_in, const int* in_sizes, int n_in,
                              void* d_out, int out_size)
{
    const float* inputs = (const float*)d_in[0];
    const float* Wx_w   = (const float*)d_in[1];
    const float* Wx_b   = (const float*)d_in[2];
    const float* U_i    = (const float*)d_in[3];
    const float* U_f    = (const float*)d_in[4];
    const float* U_o    = (const float*)d_in[5];
    const float* U_u    = (const float*)d_in[6];
    const float* convW  = (const float*)d_in[7];
    const float* conv_b = (const float*)d_in[8];
    float* out = (float*)d_out;

    cudaFuncSetAttribute(mega_kernel, cudaFuncAttributeMaxDynamicSharedMemorySize, SMEM_BYTES);
    mega_kernel<<<TGRID, THREADS, SMEM_BYTES>>>(inputs, Wx_w, Wx_b, U_i, U_f, U_o, U_u,
                                                convW, conv_b, out);
}

// round 15
// speedup vs baseline: 1.3593x; 1.0012x over previous
#include <cuda_runtime.h>
#include <cuda_fp16.h>
#include <cstdint>

// ---------------- problem constants ----------------
#define HID 64
#define INDIM 4800
#define DEPTH 14
#define NNODES 16383
#define NGEMM 256
#define NLEAF 8192
#define FIRST_LEAF 8191

// ---------------- device scratch ----------------
__device__ float g_Wx[NNODES * NGEMM];
__device__ __half g_Bh[NGEMM * INDIM];     // fp16 copy of Wx_w
__device__ float g_h[NNODES * HID];
__device__ float g_c[NNODES * HID];
__device__ float g_Uit[HID * HID];
__device__ float g_Uft[HID * HID];
__device__ float g_Uot[HID * HID];
__device__ float g_Uut[HID * HID];
__device__ float g_convWt[2 * HID * HID];
__device__ float g_v[3 * HID];
__device__ unsigned g_bar[32];

// ---------------- helpers ----------------
__device__ __forceinline__ float sigmoidf_(float x) { return 1.f / (1.f + __expf(-x)); }

__device__ __forceinline__ void mma_f16(float* d, const unsigned* a, const unsigned* b) {
    asm volatile(
        "mma.sync.aligned.m16n8k16.row.col.f32.f16.f16.f32 "
        "{%0,%1,%2,%3},{%4,%5,%6,%7},{%8,%9},{%0,%1,%2,%3};"
        : "+f"(d[0]), "+f"(d[1]), "+f"(d[2]), "+f"(d[3])
        : "r"(a[0]), "r"(a[1]), "r"(a[2]), "r"(a[3]), "r"(b[0]), "r"(b[1]));
}
__device__ __forceinline__ void ldsm_x4(unsigned& r0, unsigned& r1, unsigned& r2, unsigned& r3,
                                        unsigned addr) {
    asm volatile("ldmatrix.sync.aligned.m8n8.x4.shared.b16 {%0,%1,%2,%3}, [%4];"
                 : "=r"(r0), "=r"(r1), "=r"(r2), "=r"(r3) : "r"(addr));
}
__device__ __forceinline__ void cp_async16h(__half* smem_dst, const __half* gsrc) {
    unsigned sa = (unsigned)__cvta_generic_to_shared(smem_dst);
    asm volatile("cp.async.cg.shared.global [%0], [%1], 16;\n" :: "r"(sa), "l"(gsrc));
}
__device__ __forceinline__ void cp_commit() { asm volatile("cp.async.commit_group;\n" ::: "memory"); }

// ---------------- geometry ----------------
#define TGRID 148
#define THREADS 512
#define TWARPS 16
#define TW (TGRID * TWARPS)

// GEMM: 128x256 tile, fp16, BK=32, A x2 stages, B x4 stages (r9 proven)
#define GBLOCKS 128
#define BM 128
#define BN 256
#define BK 32
#define NK (INDIM / BK)        // 150
#define PADH 40
#define A_STH (BM * PADH)      // 5120 halves / stage (x2)
#define B_STH (BN * PADH)      // 10240 halves / stage (x4)
#define B_BASEH (2 * A_STH)
// GEMM stages = (2*5120 + 4*10240)*2 = 102400 B; epilogue Wx buffer = 131072 B

// tree smem layout (floats)
#define TS_UF 0
#define TS_UI 4096
#define TS_UO 8192
#define TS_UU 12288
#define TS_CV 16384
#define TS_WB 24576
#define SMEM_FLOATS (TS_WB + TWARPS * 640)     // 34816
#define SMEM_BYTES (SMEM_FLOATS * 4)           // 139264 B (>= 131072 epilogue, >= 102400 stages)

__device__ __forceinline__ void gridbar(int i) {
    __syncthreads();
    if (threadIdx.x == 0) {
        __threadfence();
        unsigned prev = atomicAdd(&g_bar[i], 1u);
        if (prev + 1u < (unsigned)TGRID) {
            while (*(volatile unsigned*)&g_bar[i] < (unsigned)TGRID) { __nanosleep(64); }
        }
        __threadfence();
    }
    __syncthreads();
}

// ---------------- one node-pair on one warp (weights in smem) ----------------
__device__ __forceinline__ void node_pair(int nd0, int nd1, bool two, int lane,
                                          const float* sUi, const float* sUf,
                                          const float* sUo, const float* sUu,
                                          const float* sCv, float* shw, float* scw,
                                          float* saw, float cb0, float cb1,
                                          float* __restrict__ out)
{
    ((float4*)shw)[lane]         = ((const float4*)(g_h + (size_t)(2 * nd0 + 1) * HID))[lane];
    ((float4*)(shw + 128))[lane] = ((const float4*)(g_h + (size_t)(2 * nd1 + 1) * HID))[lane];
    ((float4*)scw)[lane]         = ((const float4*)(g_c + (size_t)(2 * nd0 + 1) * HID))[lane];
    ((float4*)(scw + 128))[lane] = ((const float4*)(g_c + (size_t)(2 * nd1 + 1) * HID))[lane];
    const float* wx0 = g_Wx + (size_t)nd0 * NGEMM;
    const float* wx1 = g_Wx + (size_t)nd1 * NGEMM;
    float xf00 = wx0[64 + lane],  xf01 = wx0[96 + lane];
    float xf10 = wx1[64 + lane],  xf11 = wx1[96 + lane];
    __syncwarp();

    float a00 = cb0, a01 = cb1, a10 = cb0, a11 = cb1;
#pragma unroll 4
    for (int h = 0; h < 128; ++h) {
        float w0 = sCv[h * 64 + lane], w1 = sCv[h * 64 + lane + 32];
        float s0 = shw[h], s1 = shw[128 + h];
        a00 += s0 * w0; a01 += s0 * w1; a10 += s1 * w0; a11 += s1 * w1;
    }
    saw[lane] = a00; saw[lane + 32] = a01;
    saw[64 + lane] = a10; saw[96 + lane] = a11;

    float fl00 = xf00, fl01 = xf01, fl10 = xf10, fl11 = xf11;
    float fr00 = xf00, fr01 = xf01, fr10 = xf10, fr11 = xf11;
#pragma unroll 4
    for (int h = 0; h < 64; ++h) {
        float w0 = sUf[h * 64 + lane], w1 = sUf[h * 64 + lane + 32];
        float l0 = shw[h], r0 = shw[64 + h];
        float l1 = shw[128 + h], r1 = shw[192 + h];
        fl00 += l0 * w0; fl01 += l0 * w1; fl10 += l1 * w0; fl11 += l1 * w1;
        fr00 += r0 * w0; fr01 += r0 * w1; fr10 += r1 * w0; fr11 += r1 * w1;
    }
    float sf00 = sigmoidf_(fl00) * scw[lane]       + sigmoidf_(fr00) * scw[64 + lane];
    float sf01 = sigmoidf_(fl01) * scw[lane + 32]  + sigmoidf_(fr01) * scw[96 + lane];
    float sf10 = sigmoidf_(fl10) * scw[128 + lane] + sigmoidf_(fr10) * scw[192 + lane];
    float sf11 = sigmoidf_(fl11) * scw[160 + lane] + sigmoidf_(fr11) * scw[224 + lane];
    __syncwarp();

    float zi00 = wx0[lane],       zi01 = wx0[lane + 32];
    float zi10 = wx1[lane],       zi11 = wx1[lane + 32];
    float zo00 = wx0[128 + lane], zo01 = wx0[160 + lane];
    float zo10 = wx1[128 + lane], zo11 = wx1[160 + lane];
    float zu00 = wx0[192 + lane], zu01 = wx0[224 + lane];
    float zu10 = wx1[192 + lane], zu11 = wx1[224 + lane];
#pragma unroll 2
    for (int h = 0; h < 64; ++h) {
        float wi0 = sUi[h * 64 + lane], wi1 = sUi[h * 64 + lane + 32];
        float wo0 = sUo[h * 64 + lane], wo1 = sUo[h * 64 + lane + 32];
        float wu0 = sUu[h * 64 + lane], wu1 = sUu[h * 64 + lane + 32];
        float q0 = saw[h], q1 = saw[64 + h];
        zi00 += q0 * wi0; zi01 += q0 * wi1; zi10 += q1 * wi0; zi11 += q1 * wi1;
        zo00 += q0 * wo0; zo01 += q0 * wo1; zo10 += q1 * wo0; zo11 += q1 * wo1;
        zu00 += q0 * wu0; zu01 += q0 * wu1; zu10 += q1 * wu0; zu11 += q1 * wu1;
    }
    float c0 = sf00 + sigmoidf_(zi00) * tanhf(zu00);
    float h0 = sigmoidf_(zo00) * tanhf(c0);
    g_c[(size_t)nd0 * HID + lane] = c0;
    g_h[(size_t)nd0 * HID + lane] = h0;
    float c1 = sf01 + sigmoidf_(zi01) * tanhf(zu01);
    float h1 = sigmoidf_(zo01) * tanhf(c1);
    g_c[(size_t)nd0 * HID + lane + 32] = c1;
    g_h[(size_t)nd0 * HID + lane + 32] = h1;
    if (nd0 == 0) {
        out[lane] = h0;  out[lane + 32] = h1;
        out[64 + lane] = c0; out[96 + lane] = c1;
    }
    if (two) {
        float c2 = sf10 + sigmoidf_(zi10) * tanhf(zu10);
        g_c[(size_t)nd1 * HID + lane] = c2;
        g_h[(size_t)nd1 * HID + lane] = sigmoidf_(zo10) * tanhf(c2);
        float c3 = sf11 + sigmoidf_(zi11) * tanhf(zu11);
        g_c[(size_t)nd1 * HID + lane + 32] = c3;
        g_h[(size_t)nd1 * HID + lane + 32] = sigmoidf_(zo11) * tanhf(c3);
    }
    __syncwarp();
}

// ---------------- the mega-kernel ----------------
__global__ void __launch_bounds__(THREADS, 1)
mega_kernel(const float* __restrict__ A,
            const float* __restrict__ Wx_w,
            const float* __restrict__ Wx_b,
            const float* __restrict__ U_i, const float* __restrict__ U_f,
            const float* __restrict__ U_o, const float* __restrict__ U_u,
            const float* __restrict__ convW, const float* __restrict__ conv_b,
            float* __restrict__ out)
{
    extern __shared__ float sm[];
    __half* smh = (__half*)sm;
    const int tid  = threadIdx.x;
    const int lane = tid & 31;
    const int warp = tid >> 5;
    const int t0 = blockIdx.x * THREADS + tid;
    const int nt = TGRID * THREADS;

    // ========== phase 0: prep ==========
    for (int i = t0; i < NGEMM * INDIM / 4; i += nt) {
        float4 v = ((const float4*)Wx_w)[i];
        __half2 h0 = __floats2half2_rn(v.x, v.y);
        __half2 h1 = __floats2half2_rn(v.z, v.w);
        uint2 pk;
        pk.x = *(unsigned*)&h0; pk.y = *(unsigned*)&h1;
        ((uint2*)g_Bh)[i] = pk;
    }
    for (int idx = t0; idx < HID * HID; idx += nt) {
        int o = idx >> 6, h = idx & 63;
        g_Uit[h * HID + o] = U_i[idx];
        g_Uft[h * HID + o] = U_f[idx];
        g_Uot[h * HID + o] = U_o[idx];
        g_Uut[h * HID + o] = U_u[idx];
    }
    for (int idx = t0; idx < 2 * HID * HID; idx += nt) {
        int o = idx >> 7, kh = idx & 127;
        g_convWt[kh * HID + o] = convW[idx];
    }
    if (t0 < HID) {
        float vi = 0.f, vo = 0.f, vu = 0.f;
        for (int h = 0; h < HID; ++h) {
            float b = conv_b[h];
            vi += b * U_i[t0 * HID + h];
            vo += b * U_o[t0 * HID + h];
            vu += b * U_u[t0 * HID + h];
        }
        g_v[t0] = vi; g_v[HID + t0] = vo; g_v[2 * HID + t0] = vu;
    }
    gridbar(0);

    // ========== phase 1: fp16 GEMM (r9) with fused leaf epilogue ==========
    if (blockIdx.x < GBLOCKS) {
        const int m0 = (warp >> 2) * 32;
        const int n0 = (warp & 3) * 64;
        const int bm = blockIdx.x * BM;
        const int arow = tid >> 2;
        const int aq   = tid & 3;
        int agr = bm + arow; if (agr > NNODES - 1) agr = NNODES - 1;
        const float* agp = A + (size_t)agr * INDIM + aq * 8;

        const int rA = lane & 15;
        const int cA = (lane >> 4) * 8;
        const int rB = (lane & 7) + (lane >> 4) * 8;
        const int cB = ((lane >> 3) & 1) * 8;
        const unsigned sbase = (unsigned)__cvta_generic_to_shared(smh);
        const unsigned uA0 = ((m0 + rA) * PADH + cA) * 2;
        const unsigned uB0 = ((n0 + rB) * PADH + cB) * 2;

        float acc[2][8][4];
#pragma unroll
        for (int i = 0; i < 2; ++i)
#pragma unroll
            for (int j = 0; j < 8; ++j)
#pragma unroll
                for (int k = 0; k < 4; ++k) acc[i][j][k] = 0.f;

        float ar[8];
        auto ldgA = [&](int t) {
            const float4* p = (const float4*)(agp + t * BK);
            float4 u = p[0], v = p[1];
            ar[0] = u.x; ar[1] = u.y; ar[2] = u.z; ar[3] = u.w;
            ar[4] = v.x; ar[5] = v.y; ar[6] = v.z; ar[7] = v.w;
        };
        auto stsA = [&](int t) {
            __half2 p0 = __floats2half2_rn(ar[0], ar[1]);
            __half2 p1 = __floats2half2_rn(ar[2], ar[3]);
            __half2 p2 = __floats2half2_rn(ar[4], ar[5]);
            __half2 p3 = __floats2half2_rn(ar[6], ar[7]);
            uint4 pk;
            pk.x = *(unsigned*)&p0; pk.y = *(unsigned*)&p1;
            pk.z = *(unsigned*)&p2; pk.w = *(unsigned*)&p3;
            *(uint4*)(smh + (t & 1) * A_STH + arow * PADH + aq * 8) = pk;
        };
        auto issueB = [&](int t) {
            __half* stg = smh + B_BASEH + (t & 3) * B_STH;
            const int k0 = t * BK;
#pragma unroll
            for (int j = 0; j < 2; ++j) {
                int idx = tid + j * THREADS;
                int row = idx >> 2, c = idx & 3;
                cp_async16h(stg + row * PADH + c * 8,
                            g_Bh + (size_t)row * INDIM + k0 + c * 8);
            }
            cp_commit();
        };

        ldgA(0);
        issueB(0); issueB(1);

        for (int s = 0; s < NK; ++s) {
            stsA(s);
            if (s + 1 < NK) ldgA(s + 1);
            if (s + 2 < NK) issueB(s + 2); else cp_commit();
            asm volatile("cp.async.wait_group 2;" ::: "memory");
            __syncthreads();

            const unsigned stA = sbase + ((s & 1) * A_STH) * 2;
            const unsigned stB = sbase + (B_BASEH + (s & 3) * B_STH) * 2;

#pragma unroll
            for (int ks = 0; ks < 2; ++ks) {
                unsigned af[2][4], bf[8][2];
                ldsm_x4(af[0][0], af[0][1], af[0][2], af[0][3],
                        stA + uA0 + ks * 32);
                ldsm_x4(af[1][0], af[1][1], af[1][2], af[1][3],
                        stA + uA0 + 16 * PADH * 2 + ks * 32);
#pragma unroll
                for (int j = 0; j < 4; ++j)
                    ldsm_x4(bf[2 * j][0], bf[2 * j][1], bf[2 * j + 1][0], bf[2 * j + 1][1],
                            stB + uB0 + j * 16 * PADH * 2 + ks * 32);
#pragma unroll
                for (int im = 0; im < 2; ++im)
#pragma unroll
                    for (int in = 0; in < 8; ++in)
                        mma_f16(acc[im][in], af[im], bf[in]);
            }
        }

        // ---- epilogue: acc+bias -> smem buffer [128][256], then per-row dispatch ----
        __syncthreads();                 // all warps done with stage smem
        float* swx = sm;                 // 128*256 floats = 131072 B
        const int gid = lane >> 2, tig = lane & 3;
#pragma unroll
        for (int im = 0; im < 2; ++im) {
#pragma unroll
            for (int in = 0; in < 8; ++in) {
                int r0 = m0 + im * 16 + gid;
                int cg = n0 + in * 8 + tig * 2;
                float b0 = Wx_b[cg], b1 = Wx_b[cg + 1];
                swx[r0 * 256 + cg]           = acc[im][in][0] + b0;
                swx[r0 * 256 + cg + 1]       = acc[im][in][1] + b1;
                swx[(r0 + 8) * 256 + cg]     = acc[im][in][2] + b0;
                swx[(r0 + 8) * 256 + cg + 1] = acc[im][in][3] + b1;
            }
        }
        __syncthreads();

#pragma unroll
        for (int k = 0; k < 16; ++k) {
            int idx = tid + k * THREADS;        // 0..8191
            int row = idx >> 6, o = idx & 63;
            int node = bm + row;
            if (node < FIRST_LEAF) {
                // internal node: store all four gates to g_Wx (coalesced per gate)
                float* dst = g_Wx + (size_t)node * NGEMM;
                const float* src = swx + row * 256;
                dst[o]       = src[o];
                dst[64 + o]  = src[64 + o];
                dst[128 + o] = src[128 + o];
                dst[192 + o] = src[192 + o];
            } else if (node < NNODES) {
                // leaf: compute h,c directly
                const float* src = swx + row * 256;
                float zi = src[o]       + g_v[o];
                float zo = src[128 + o] + g_v[64 + o];
                float zu = src[192 + o] + g_v[128 + o];
                float c = sigmoidf_(zi) * tanhf(zu);
                g_c[(size_t)node * HID + o] = c;
                g_h[(size_t)node * HID + o] = sigmoidf_(zo) * tanhf(c);
            }
        }
        __syncthreads();
    }

    // stage tree weights into smem
    for (int i = tid; i < 4096; i += THREADS) {
        sm[TS_UF + i] = g_Uft[i];
        sm[TS_UI + i] = g_Uit[i];
        sm[TS_UO + i] = g_Uot[i];
        sm[TS_UU + i] = g_Uut[i];
    }
    for (int i = tid; i < 8192; i += THREADS) sm[TS_CV + i] = g_convWt[i];
    int bi = 1;
    gridbar(bi++);

    // ========== phase 2: levels d = 12..5, grid-wide ==========
    const int gw = blockIdx.x * TWARPS + warp;
    float* shw = sm + TS_WB + warp * 640;
    float* scw = shw + 256;
    float* saw = shw + 512;
    const float cb0 = conv_b[lane], cb1 = conv_b[lane + 32];

    for (int d = DEPTH - 2; d >= 5; --d) {
        const int n = 1 << d, start = n - 1;
        for (int j = gw * 2; j < n; j += TW * 2) {
            const bool two = (j + 1 < n);
            node_pair(start + j, start + j + (two ? 1 : 0), two, lane,
                      sm + TS_UI, sm + TS_UF, sm + TS_UO, sm + TS_UU, sm + TS_CV,
                      shw, scw, saw, cb0, cb1, out);
        }
        gridbar(bi++);          // bi 2..9
    }

    // ========== phase 3: levels d = 4..0, block 0 only ==========
    __syncthreads();
    if (blockIdx.x != 0) {
        if (tid == 0) { __threadfence(); atomicAdd(&g_bar[bi], 1u); }
        return;
    }
    if (tid == 0) {
        __threadfence();
        atomicAdd(&g_bar[bi], 1u);
        while (*(volatile unsigned*)&g_bar[bi] < (unsigned)TGRID) { __nanosleep(64); }
        __threadfence();
    }
    __syncthreads();

    for (int d = 4; d >= 0; --d) {
        const int n = 1 << d, start = n - 1;
        for (int j = warp * 2; j < n; j += TWARPS * 2) {
            const bool two = (j + 1 < n);
            node_pair(start + j, start + j + (two ? 1 : 0), two, lane,
                      sm + TS_UI, sm + TS_UF, sm + TS_UO, sm + TS_UU, sm + TS_CV,
                      shw, scw, saw, cb0, cb1, out);
        }
        __syncthreads();
    }

    if (tid < 32) g_bar[tid] = 0;   // reset for graph replay
}

// ---------------- launch ----------------
extern "C" void kernel_launch(void* const* d_in, const int* in_sizes, int n_in,
                              void* d_out, int out_size)
{
    const float* inputs = (const float*)d_in[0];
    const float* Wx_w   = (const float*)d_in[1];
    const float* Wx_b   = (const float*)d_in[2];
    const float* U_i    = (const float*)d_in[3];
    const float* U_f    = (const float*)d_in[4];
    const float* U_o    = (const float*)d_in[5];
    const float* U_u    = (const float*)d_in[6];
    const float* convW  = (const float*)d_in[7];
    const float* conv_b = (const float*)d_in[8];
    float* out = (float*)d_out;

    cudaFuncSetAttribute(mega_kernel, cudaFuncAttributeMaxDynamicSharedMemorySize, SMEM_BYTES);
    mega_kernel<<<TGRID, THREADS, SMEM_BYTES>>>(inputs, Wx_w, Wx_b, U_i, U_f, U_o, U_u,
                                                convW, conv_b, out);
}

// round 16
// speedup vs baseline: 1.4954x; 1.1001x over previous
#include <cuda_runtime.h>
#include <cuda_fp16.h>
#include <cstdint>

// ---------------- problem constants ----------------
#define HID 64
#define INDIM 4800
#define DEPTH 14
#define NNODES 16383
#define NGEMM 256
#define NLEAF 8192
#define FIRST_LEAF 8191

// ---------------- device scratch ----------------
__device__ float g_Wx[NNODES * NGEMM];
__device__ __half g_Bh[NGEMM * INDIM];     // fp16 copy of Wx_w
__device__ float g_h[NNODES * HID];
__device__ float g_c[NNODES * HID];
__device__ float g_Uit[HID * HID];
__device__ float g_Uft[HID * HID];
__device__ float g_Uot[HID * HID];
__device__ float g_Uut[HID * HID];
__device__ float g_convWt[2 * HID * HID];
__device__ float g_v[3 * HID];
__device__ unsigned g_bar[32];

// ---------------- helpers ----------------
__device__ __forceinline__ float sigmoidf_(float x) { return 1.f / (1.f + __expf(-x)); }

__device__ __forceinline__ void mma_f16(float* d, const unsigned* a, const unsigned* b) {
    asm volatile(
        "mma.sync.aligned.m16n8k16.row.col.f32.f16.f16.f32 "
        "{%0,%1,%2,%3},{%4,%5,%6,%7},{%8,%9},{%0,%1,%2,%3};"
        : "+f"(d[0]), "+f"(d[1]), "+f"(d[2]), "+f"(d[3])
        : "r"(a[0]), "r"(a[1]), "r"(a[2]), "r"(a[3]), "r"(b[0]), "r"(b[1]));
}
__device__ __forceinline__ void ldsm_x4(unsigned& r0, unsigned& r1, unsigned& r2, unsigned& r3,
                                        unsigned addr) {
    asm volatile("ldmatrix.sync.aligned.m8n8.x4.shared.b16 {%0,%1,%2,%3}, [%4];"
                 : "=r"(r0), "=r"(r1), "=r"(r2), "=r"(r3) : "r"(addr));
}
__device__ __forceinline__ void cp_async16h(__half* smem_dst, const __half* gsrc) {
    unsigned sa = (unsigned)__cvta_generic_to_shared(smem_dst);
    asm volatile("cp.async.cg.shared.global [%0], [%1], 16;\n" :: "r"(sa), "l"(gsrc));
}
__device__ __forceinline__ void cp_commit() { asm volatile("cp.async.commit_group;\n" ::: "memory"); }

// ---------------- geometry ----------------
#define TGRID 148
#define THREADS 512
#define TWARPS 16

// GEMM: 128x256 tile, fp16, BK=32, A x2 stages, B x4 stages (r9/r15 proven)
#define GBLOCKS 128
#define BM 128
#define BN 256
#define BK 32
#define NK (INDIM / BK)        // 150
#define PADH 40
#define A_STH (BM * PADH)      // 5120 halves / stage (x2)
#define B_STH (BN * PADH)      // 10240 halves / stage (x4)
#define B_BASEH (2 * A_STH)

// tree smem layout (floats)
#define TS_UF 0
#define TS_UI 4096
#define TS_UO 8192
#define TS_UU 12288
#define TS_CV 16384
#define TS_WB 24576
#define SMEM_FLOATS (TS_WB + TWARPS * 640)     // 34816
#define SMEM_BYTES (SMEM_FLOATS * 4)           // 139264 B

__device__ __forceinline__ void gridbar(int i) {
    __syncthreads();
    if (threadIdx.x == 0) {
        __threadfence();
        unsigned prev = atomicAdd(&g_bar[i], 1u);
        if (prev + 1u < (unsigned)TGRID) {
            while (*(volatile unsigned*)&g_bar[i] < (unsigned)TGRID) { __nanosleep(64); }
        }
        __threadfence();
    }
    __syncthreads();
}

// ---------------- one node-pair on one warp (weights in smem) ----------------
__device__ __forceinline__ void node_pair(int nd0, int nd1, bool two, int lane,
                                          const float* sUi, const float* sUf,
                                          const float* sUo, const float* sUu,
                                          const float* sCv, float* shw, float* scw,
                                          float* saw, float cb0, float cb1,
                                          float* __restrict__ out)
{
    ((float4*)shw)[lane]         = ((const float4*)(g_h + (size_t)(2 * nd0 + 1) * HID))[lane];
    ((float4*)(shw + 128))[lane] = ((const float4*)(g_h + (size_t)(2 * nd1 + 1) * HID))[lane];
    ((float4*)scw)[lane]         = ((const float4*)(g_c + (size_t)(2 * nd0 + 1) * HID))[lane];
    ((float4*)(scw + 128))[lane] = ((const float4*)(g_c + (size_t)(2 * nd1 + 1) * HID))[lane];
    const float* wx0 = g_Wx + (size_t)nd0 * NGEMM;
    const float* wx1 = g_Wx + (size_t)nd1 * NGEMM;
    float xf00 = wx0[64 + lane],  xf01 = wx0[96 + lane];
    float xf10 = wx1[64 + lane],  xf11 = wx1[96 + lane];
    __syncwarp();

    float a00 = cb0, a01 = cb1, a10 = cb0, a11 = cb1;
#pragma unroll 4
    for (int h = 0; h < 128; ++h) {
        float w0 = sCv[h * 64 + lane], w1 = sCv[h * 64 + lane + 32];
        float s0 = shw[h], s1 = shw[128 + h];
        a00 += s0 * w0; a01 += s0 * w1; a10 += s1 * w0; a11 += s1 * w1;
    }
    saw[lane] = a00; saw[lane + 32] = a01;
    saw[64 + lane] = a10; saw[96 + lane] = a11;

    float fl00 = xf00, fl01 = xf01, fl10 = xf10, fl11 = xf11;
    float fr00 = xf00, fr01 = xf01, fr10 = xf10, fr11 = xf11;
#pragma unroll 4
    for (int h = 0; h < 64; ++h) {
        float w0 = sUf[h * 64 + lane], w1 = sUf[h * 64 + lane + 32];
        float l0 = shw[h], r0 = shw[64 + h];
        float l1 = shw[128 + h], r1 = shw[192 + h];
        fl00 += l0 * w0; fl01 += l0 * w1; fl10 += l1 * w0; fl11 += l1 * w1;
        fr00 += r0 * w0; fr01 += r0 * w1; fr10 += r1 * w0; fr11 += r1 * w1;
    }
    float sf00 = sigmoidf_(fl00) * scw[lane]       + sigmoidf_(fr00) * scw[64 + lane];
    float sf01 = sigmoidf_(fl01) * scw[lane + 32]  + sigmoidf_(fr01) * scw[96 + lane];
    float sf10 = sigmoidf_(fl10) * scw[128 + lane] + sigmoidf_(fr10) * scw[192 + lane];
    float sf11 = sigmoidf_(fl11) * scw[160 + lane] + sigmoidf_(fr11) * scw[224 + lane];
    __syncwarp();

    float zi00 = wx0[lane],       zi01 = wx0[lane + 32];
    float zi10 = wx1[lane],       zi11 = wx1[lane + 32];
    float zo00 = wx0[128 + lane], zo01 = wx0[160 + lane];
    float zo10 = wx1[128 + lane], zo11 = wx1[160 + lane];
    float zu00 = wx0[192 + lane], zu01 = wx0[224 + lane];
    float zu10 = wx1[192 + lane], zu11 = wx1[224 + lane];
#pragma unroll 2
    for (int h = 0; h < 64; ++h) {
        float wi0 = sUi[h * 64 + lane], wi1 = sUi[h * 64 + lane + 32];
        float wo0 = sUo[h * 64 + lane], wo1 = sUo[h * 64 + lane + 32];
        float wu0 = sUu[h * 64 + lane], wu1 = sUu[h * 64 + lane + 32];
        float q0 = saw[h], q1 = saw[64 + h];
        zi00 += q0 * wi0; zi01 += q0 * wi1; zi10 += q1 * wi0; zi11 += q1 * wi1;
        zo00 += q0 * wo0; zo01 += q0 * wo1; zo10 += q1 * wo0; zo11 += q1 * wo1;
        zu00 += q0 * wu0; zu01 += q0 * wu1; zu10 += q1 * wu0; zu11 += q1 * wu1;
    }
    float c0 = sf00 + sigmoidf_(zi00) * tanhf(zu00);
    float h0 = sigmoidf_(zo00) * tanhf(c0);
    g_c[(size_t)nd0 * HID + lane] = c0;
    g_h[(size_t)nd0 * HID + lane] = h0;
    float c1 = sf01 + sigmoidf_(zi01) * tanhf(zu01);
    float h1 = sigmoidf_(zo01) * tanhf(c1);
    g_c[(size_t)nd0 * HID + lane + 32] = c1;
    g_h[(size_t)nd0 * HID + lane + 32] = h1;
    if (nd0 == 0) {
        out[lane] = h0;  out[lane + 32] = h1;
        out[64 + lane] = c0; out[96 + lane] = c1;
    }
    if (two) {
        float c2 = sf10 + sigmoidf_(zi10) * tanhf(zu10);
        g_c[(size_t)nd1 * HID + lane] = c2;
        g_h[(size_t)nd1 * HID + lane] = sigmoidf_(zo10) * tanhf(c2);
        float c3 = sf11 + sigmoidf_(zi11) * tanhf(zu11);
        g_c[(size_t)nd1 * HID + lane + 32] = c3;
        g_h[(size_t)nd1 * HID + lane + 32] = sigmoidf_(zo11) * tanhf(c3);
    }
    __syncwarp();
}

// ---------------- the mega-kernel ----------------
__global__ void __launch_bounds__(THREADS, 1)
mega_kernel(const float* __restrict__ A,
            const float* __restrict__ Wx_w,
            const float* __restrict__ Wx_b,
            const float* __restrict__ U_i, const float* __restrict__ U_f,
            const float* __restrict__ U_o, const float* __restrict__ U_u,
            const float* __restrict__ convW, const float* __restrict__ conv_b,
            float* __restrict__ out)
{
    extern __shared__ float sm[];
    __half* smh = (__half*)sm;
    const int tid  = threadIdx.x;
    const int lane = tid & 31;
    const int warp = tid >> 5;
    const int t0 = blockIdx.x * THREADS + tid;
    const int nt = TGRID * THREADS;

    // ========== phase 0: prep ==========
    for (int i = t0; i < NGEMM * INDIM / 4; i += nt) {
        float4 v = ((const float4*)Wx_w)[i];
        __half2 h0 = __floats2half2_rn(v.x, v.y);
        __half2 h1 = __floats2half2_rn(v.z, v.w);
        uint2 pk;
        pk.x = *(unsigned*)&h0; pk.y = *(unsigned*)&h1;
        ((uint2*)g_Bh)[i] = pk;
    }
    for (int idx = t0; idx < HID * HID; idx += nt) {
        int o = idx >> 6, h = idx & 63;
        g_Uit[h * HID + o] = U_i[idx];
        g_Uft[h * HID + o] = U_f[idx];
        g_Uot[h * HID + o] = U_o[idx];
        g_Uut[h * HID + o] = U_u[idx];
    }
    for (int idx = t0; idx < 2 * HID * HID; idx += nt) {
        int o = idx >> 7, kh = idx & 127;
        g_convWt[kh * HID + o] = convW[idx];
    }
    if (t0 < HID) {
        float vi = 0.f, vo = 0.f, vu = 0.f;
        for (int h = 0; h < HID; ++h) {
            float b = conv_b[h];
            vi += b * U_i[t0 * HID + h];
            vo += b * U_o[t0 * HID + h];
            vu += b * U_u[t0 * HID + h];
        }
        g_v[t0] = vi; g_v[HID + t0] = vo; g_v[2 * HID + t0] = vu;
    }
    gridbar(0);

    // ========== phase 1: fp16 GEMM with fused leaf epilogue ==========
    if (blockIdx.x < GBLOCKS) {
        const int m0 = (warp >> 2) * 32;
        const int n0 = (warp & 3) * 64;
        const int bm = blockIdx.x * BM;
        const int arow = tid >> 2;
        const int aq   = tid & 3;
        int agr = bm + arow; if (agr > NNODES - 1) agr = NNODES - 1;
        const float* agp = A + (size_t)agr * INDIM + aq * 8;

        const int rA = lane & 15;
        const int cA = (lane >> 4) * 8;
        const int rB = (lane & 7) + (lane >> 4) * 8;
        const int cB = ((lane >> 3) & 1) * 8;
        const unsigned sbase = (unsigned)__cvta_generic_to_shared(smh);
        const unsigned uA0 = ((m0 + rA) * PADH + cA) * 2;
        const unsigned uB0 = ((n0 + rB) * PADH + cB) * 2;

        float acc[2][8][4];
#pragma unroll
        for (int i = 0; i < 2; ++i)
#pragma unroll
            for (int j = 0; j < 8; ++j)
#pragma unroll
                for (int k = 0; k < 4; ++k) acc[i][j][k] = 0.f;

        float ar[8];
        auto ldgA = [&](int t) {
            const float4* p = (const float4*)(agp + t * BK);
            float4 u = p[0], v = p[1];
            ar[0] = u.x; ar[1] = u.y; ar[2] = u.z; ar[3] = u.w;
            ar[4] = v.x; ar[5] = v.y; ar[6] = v.z; ar[7] = v.w;
        };
        auto stsA = [&](int t) {
            __half2 p0 = __floats2half2_rn(ar[0], ar[1]);
            __half2 p1 = __floats2half2_rn(ar[2], ar[3]);
            __half2 p2 = __floats2half2_rn(ar[4], ar[5]);
            __half2 p3 = __floats2half2_rn(ar[6], ar[7]);
            uint4 pk;
            pk.x = *(unsigned*)&p0; pk.y = *(unsigned*)&p1;
            pk.z = *(unsigned*)&p2; pk.w = *(unsigned*)&p3;
            *(uint4*)(smh + (t & 1) * A_STH + arow * PADH + aq * 8) = pk;
        };
        auto issueB = [&](int t) {
            __half* stg = smh + B_BASEH + (t & 3) * B_STH;
            const int k0 = t * BK;
#pragma unroll
            for (int j = 0; j < 2; ++j) {
                int idx = tid + j * THREADS;
                int row = idx >> 2, c = idx & 3;
                cp_async16h(stg + row * PADH + c * 8,
                            g_Bh + (size_t)row * INDIM + k0 + c * 8);
            }
            cp_commit();
        };

        ldgA(0);
        issueB(0); issueB(1);

        for (int s = 0; s < NK; ++s) {
            stsA(s);
            if (s + 1 < NK) ldgA(s + 1);
            if (s + 2 < NK) issueB(s + 2); else cp_commit();
            asm volatile("cp.async.wait_group 2;" ::: "memory");
            __syncthreads();

            const unsigned stA = sbase + ((s & 1) * A_STH) * 2;
            const unsigned stB = sbase + (B_BASEH + (s & 3) * B_STH) * 2;

#pragma unroll
            for (int ks = 0; ks < 2; ++ks) {
                unsigned af[2][4], bf[8][2];
                ldsm_x4(af[0][0], af[0][1], af[0][2], af[0][3],
                        stA + uA0 + ks * 32);
                ldsm_x4(af[1][0], af[1][1], af[1][2], af[1][3],
                        stA + uA0 + 16 * PADH * 2 + ks * 32);
#pragma unroll
                for (int j = 0; j < 4; ++j)
                    ldsm_x4(bf[2 * j][0], bf[2 * j][1], bf[2 * j + 1][0], bf[2 * j + 1][1],
                            stB + uB0 + j * 16 * PADH * 2 + ks * 32);
#pragma unroll
                for (int im = 0; im < 2; ++im)
#pragma unroll
                    for (int in = 0; in < 8; ++in)
                        mma_f16(acc[im][in], af[im], bf[in]);
            }
        }

        // ---- epilogue: acc+bias -> smem buffer, leaf rows computed directly ----
        __syncthreads();
        float* swx = sm;
        const int gid = lane >> 2, tig = lane & 3;
#pragma unroll
        for (int im = 0; im < 2; ++im) {
#pragma unroll
            for (int in = 0; in < 8; ++in) {
                int r0 = m0 + im * 16 + gid;
                int cg = n0 + in * 8 + tig * 2;
                float b0 = Wx_b[cg], b1 = Wx_b[cg + 1];
                swx[r0 * 256 + cg]           = acc[im][in][0] + b0;
                swx[r0 * 256 + cg + 1]       = acc[im][in][1] + b1;
                swx[(r0 + 8) * 256 + cg]     = acc[im][in][2] + b0;
                swx[(r0 + 8) * 256 + cg + 1] = acc[im][in][3] + b1;
            }
        }
        __syncthreads();

#pragma unroll
        for (int k = 0; k < 16; ++k) {
            int idx = tid + k * THREADS;
            int row = idx >> 6, o = idx & 63;
            int node = bm + row;
            if (node < FIRST_LEAF) {
                float* dst = g_Wx + (size_t)node * NGEMM;
                const float* src = swx + row * 256;
                dst[o]       = src[o];
                dst[64 + o]  = src[64 + o];
                dst[128 + o] = src[128 + o];
                dst[192 + o] = src[192 + o];
            } else if (node < NNODES) {
                const float* src = swx + row * 256;
                float zi = src[o]       + g_v[o];
                float zo = src[128 + o] + g_v[64 + o];
                float zu = src[192 + o] + g_v[128 + o];
                float c = sigmoidf_(zi) * tanhf(zu);
                g_c[(size_t)node * HID + o] = c;
                g_h[(size_t)node * HID + o] = sigmoidf_(zo) * tanhf(c);
            }
        }
        __syncthreads();
    }

    // stage tree weights into smem
    for (int i = tid; i < 4096; i += THREADS) {
        sm[TS_UF + i] = g_Uft[i];
        sm[TS_UI + i] = g_Uit[i];
        sm[TS_UO + i] = g_Uot[i];
        sm[TS_UU + i] = g_Uut[i];
    }
    for (int i = tid; i < 8192; i += THREADS) sm[TS_CV + i] = g_convWt[i];
    gridbar(1);

    // ========== phase 2: subtrees d = 12..7, one subtree per block ==========
    float* shw = sm + TS_WB + warp * 640;
    float* scw = shw + 256;
    float* saw = shw + 512;
    const float cb0 = conv_b[lane], cb1 = conv_b[lane + 32];

    if (blockIdx.x < GBLOCKS) {
        // block b owns subtree rooted at node 127 + b (depth 7)
        const int r1 = 128 + blockIdx.x;       // root index + 1
        for (int d = 12; d >= 7; --d) {
            const int n = 1 << (d - 7);        // 32,16,8,4,2,1
            const int start = (r1 << (d - 7)) - 1;
            if (n == 1) {
                if (warp == 0)
                    node_pair(start, start, false, lane,
                              sm + TS_UI, sm + TS_UF, sm + TS_UO, sm + TS_UU, sm + TS_CV,
                              shw, scw, saw, cb0, cb1, out);
            } else {
                for (int j = warp * 2; j < n; j += TWARPS * 2) {
                    node_pair(start + j, start + j + 1, true, lane,
                              sm + TS_UI, sm + TS_UF, sm + TS_UO, sm + TS_UU, sm + TS_CV,
                              shw, scw, saw, cb0, cb1, out);
                }
            }
            __syncthreads();
        }
    }
    gridbar(2);

    // ========== phase 3: levels d = 6..0, block 0 only ==========
    if (blockIdx.x != 0) {
        if (tid == 0) { __threadfence(); atomicAdd(&g_bar[3], 1u); }
        return;
    }
    if (tid == 0) {
        __threadfence();
        atomicAdd(&g_bar[3], 1u);
        while (*(volatile unsigned*)&g_bar[3] < (unsigned)TGRID) { __nanosleep(64); }
        __threadfence();
    }
    __syncthreads();

    for (int d = 6; d >= 0; --d) {
        const int n = 1 << d, start = n - 1;
        if (n == 1) {
            if (warp == 0)
                node_pair(0, 0, false, lane,
                          sm + TS_UI, sm + TS_UF, sm + TS_UO, sm + TS_UU, sm + TS_CV,
                          shw, scw, saw, cb0, cb1, out);
        } else {
            for (int j = warp * 2; j < n; j += TWARPS * 2) {
                node_pair(start + j, start + j + 1, true, lane,
                          sm + TS_UI, sm + TS_UF, sm + TS_UO, sm + TS_UU, sm + TS_CV,
                          shw, scw, saw, cb0, cb1, out);
            }
        }
        __syncthreads();
    }

    if (tid < 32) g_bar[tid] = 0;   // reset for graph replay
}

// ---------------- launch ----------------
extern "C" void kernel_launch(void* const* d_in, const int* in_sizes, int n_in,
                              void* d_out, int out_size)
{
    const float* inputs = (const float*)d_in[0];
    const float* Wx_w   = (const float*)d_in[1];
    const float* Wx_b   = (const float*)d_in[2];
    const float* U_i    = (const float*)d_in[3];
    const float* U_f    = (const float*)d_in[4];
    const float* U_o    = (const float*)d_in[5];
    const float* U_u    = (const float*)d_in[6];
    const float* convW  = (const float*)d_in[7];
    const float* conv_b = (const float*)d_in[8];
    float* out = (float*)d_out;

    cudaFuncSetAttribute(mega_kernel, cudaFuncAttributeMaxDynamicSharedMemorySize, SMEM_BYTES);
    mega_kernel<<<TGRID, THREADS, SMEM_BYTES>>>(inputs, Wx_w, Wx_b, U_i, U_f, U_o, U_u,
                                                convW, conv_b, out);
}

// round 17
// speedup vs baseline: 1.5217x; 1.0176x over previous
#include <cuda_runtime.h>
#include <cuda_fp16.h>
#include <cstdint>

// ---------------- problem constants ----------------
#define HID 64
#define INDIM 4800
#define DEPTH 14
#define NNODES 16383
#define NGEMM 256
#define NLEAF 8192
#define FIRST_LEAF 8191

// ---------------- device scratch ----------------
__device__ float g_Wx[NNODES * NGEMM];
__device__ __half g_Bh[NGEMM * INDIM];     // fp16 copy of Wx_w
__device__ float g_h[NNODES * HID];
__device__ float g_c[NNODES * HID];
__device__ float g_Uit[HID * HID];
__device__ float g_Uft[HID * HID];
__device__ float g_Uot[HID * HID];
__device__ float g_Uut[HID * HID];
__device__ float g_convWt[2 * HID * HID];
__device__ float g_v[3 * HID];
__device__ unsigned g_bar[32];

// ---------------- helpers ----------------
__device__ __forceinline__ float sigmoidf_(float x) { return 1.f / (1.f + __expf(-x)); }

__device__ __forceinline__ void mma_f16(float* d, const unsigned* a, const unsigned* b) {
    asm volatile(
        "mma.sync.aligned.m16n8k16.row.col.f32.f16.f16.f32 "
        "{%0,%1,%2,%3},{%4,%5,%6,%7},{%8,%9},{%0,%1,%2,%3};"
        : "+f"(d[0]), "+f"(d[1]), "+f"(d[2]), "+f"(d[3])
        : "r"(a[0]), "r"(a[1]), "r"(a[2]), "r"(a[3]), "r"(b[0]), "r"(b[1]));
}
__device__ __forceinline__ void ldsm_x4(unsigned& r0, unsigned& r1, unsigned& r2, unsigned& r3,
                                        unsigned addr) {
    asm volatile("ldmatrix.sync.aligned.m8n8.x4.shared.b16 {%0,%1,%2,%3}, [%4];"
                 : "=r"(r0), "=r"(r1), "=r"(r2), "=r"(r3) : "r"(addr));
}
__device__ __forceinline__ void cp_async16h(__half* smem_dst, const __half* gsrc) {
    unsigned sa = (unsigned)__cvta_generic_to_shared(smem_dst);
    asm volatile("cp.async.cg.shared.global [%0], [%1], 16;\n" :: "r"(sa), "l"(gsrc));
}
__device__ __forceinline__ void cp_commit() { asm volatile("cp.async.commit_group;\n" ::: "memory"); }

// ---------------- geometry ----------------
#define TGRID 148
#define THREADS 512
#define TWARPS 16

// GEMM: 128x256 tile, fp16, BK=32, A x2 stages, B x4 stages (proven r9/r15/r16)
#define GBLOCKS 128
#define BM 128
#define BN 256
#define BK 32
#define NK (INDIM / BK)        // 150
#define PADH 40
#define A_STH (BM * PADH)      // 5120 halves / stage (x2)
#define B_STH (BN * PADH)      // 10240 halves / stage (x4)
#define B_BASEH (2 * A_STH)

// tree smem layout (floats)
#define TS_UF 0
#define TS_UI 4096
#define TS_UO 8192
#define TS_UU 12288
#define TS_CV 16384
#define TS_WB 24576
#define SMEM_FLOATS (TS_WB + TWARPS * 640)     // 34816
#define SMEM_BYTES (SMEM_FLOATS * 4)           // 139264 B

__device__ __forceinline__ void gridbar(int i) {
    __syncthreads();
    if (threadIdx.x == 0) {
        __threadfence();
        unsigned prev = atomicAdd(&g_bar[i], 1u);
        if (prev + 1u < (unsigned)TGRID) {
            while (*(volatile unsigned*)&g_bar[i] < (unsigned)TGRID) { __nanosleep(64); }
        }
        __threadfence();
    }
    __syncthreads();
}

// ---------------- one node-pair on one warp (weights in smem) ----------------
// All gmem loads (children h/c + all 4 gate rows of both nodes) issued up front
// so their latency hides behind the conv/U dot-product loops.
__device__ __forceinline__ void node_pair(int nd0, int nd1, bool two, int lane,
                                          const float* sUi, const float* sUf,
                                          const float* sUo, const float* sUu,
                                          const float* sCv, float* shw, float* scw,
                                          float* saw, float cb0, float cb1,
                                          float* __restrict__ out)
{
    ((float4*)shw)[lane]         = ((const float4*)(g_h + (size_t)(2 * nd0 + 1) * HID))[lane];
    ((float4*)(shw + 128))[lane] = ((const float4*)(g_h + (size_t)(2 * nd1 + 1) * HID))[lane];
    ((float4*)scw)[lane]         = ((const float4*)(g_c + (size_t)(2 * nd0 + 1) * HID))[lane];
    ((float4*)(scw + 128))[lane] = ((const float4*)(g_c + (size_t)(2 * nd1 + 1) * HID))[lane];
    const float* wx0 = g_Wx + (size_t)nd0 * NGEMM;
    const float* wx1 = g_Wx + (size_t)nd1 * NGEMM;
    // hoisted gate pre-activation loads (12 LDGs issued before any compute)
    float xf00 = wx0[64 + lane],  xf01 = wx0[96 + lane];
    float xf10 = wx1[64 + lane],  xf11 = wx1[96 + lane];
    float zi00 = wx0[lane],       zi01 = wx0[lane + 32];
    float zi10 = wx1[lane],       zi11 = wx1[lane + 32];
    float zo00 = wx0[128 + lane], zo01 = wx0[160 + lane];
    float zo10 = wx1[128 + lane], zo11 = wx1[160 + lane];
    float zu00 = wx0[192 + lane], zu01 = wx0[224 + lane];
    float zu10 = wx1[192 + lane], zu11 = wx1[224 + lane];
    __syncwarp();

    float a00 = cb0, a01 = cb1, a10 = cb0, a11 = cb1;
#pragma unroll 4
    for (int h = 0; h < 128; ++h) {
        float w0 = sCv[h * 64 + lane], w1 = sCv[h * 64 + lane + 32];
        float s0 = shw[h], s1 = shw[128 + h];
        a00 += s0 * w0; a01 += s0 * w1; a10 += s1 * w0; a11 += s1 * w1;
    }
    saw[lane] = a00; saw[lane + 32] = a01;
    saw[64 + lane] = a10; saw[96 + lane] = a11;

    float fl00 = xf00, fl01 = xf01, fl10 = xf10, fl11 = xf11;
    float fr00 = xf00, fr01 = xf01, fr10 = xf10, fr11 = xf11;
#pragma unroll 4
    for (int h = 0; h < 64; ++h) {
        float w0 = sUf[h * 64 + lane], w1 = sUf[h * 64 + lane + 32];
        float l0 = shw[h], r0 = shw[64 + h];
        float l1 = shw[128 + h], r1 = shw[192 + h];
        fl00 += l0 * w0; fl01 += l0 * w1; fl10 += l1 * w0; fl11 += l1 * w1;
        fr00 += r0 * w0; fr01 += r0 * w1; fr10 += r1 * w0; fr11 += r1 * w1;
    }
    float sf00 = sigmoidf_(fl00) * scw[lane]       + sigmoidf_(fr00) * scw[64 + lane];
    float sf01 = sigmoidf_(fl01) * scw[lane + 32]  + sigmoidf_(fr01) * scw[96 + lane];
    float sf10 = sigmoidf_(fl10) * scw[128 + lane] + sigmoidf_(fr10) * scw[192 + lane];
    float sf11 = sigmoidf_(fl11) * scw[160 + lane] + sigmoidf_(fr11) * scw[224 + lane];
    __syncwarp();

#pragma unroll 2
    for (int h = 0; h < 64; ++h) {
        float wi0 = sUi[h * 64 + lane], wi1 = sUi[h * 64 + lane + 32];
        float wo0 = sUo[h * 64 + lane], wo1 = sUo[h * 64 + lane + 32];
        float wu0 = sUu[h * 64 + lane], wu1 = sUu[h * 64 + lane + 32];
        float q0 = saw[h], q1 = saw[64 + h];
        zi00 += q0 * wi0; zi01 += q0 * wi1; zi10 += q1 * wi0; zi11 += q1 * wi1;
        zo00 += q0 * wo0; zo01 += q0 * wo1; zo10 += q1 * wo0; zo11 += q1 * wo1;
        zu00 += q0 * wu0; zu01 += q0 * wu1; zu10 += q1 * wu0; zu11 += q1 * wu1;
    }
    float c0 = sf00 + sigmoidf_(zi00) * tanhf(zu00);
    float h0 = sigmoidf_(zo00) * tanhf(c0);
    g_c[(size_t)nd0 * HID + lane] = c0;
    g_h[(size_t)nd0 * HID + lane] = h0;
    float c1 = sf01 + sigmoidf_(zi01) * tanhf(zu01);
    float h1 = sigmoidf_(zo01) * tanhf(c1);
    g_c[(size_t)nd0 * HID + lane + 32] = c1;
    g_h[(size_t)nd0 * HID + lane + 32] = h1;
    if (nd0 == 0) {
        out[lane] = h0;  out[lane + 32] = h1;
        out[64 + lane] = c0; out[96 + lane] = c1;
    }
    if (two) {
        float c2 = sf10 + sigmoidf_(zi10) * tanhf(zu10);
        g_c[(size_t)nd1 * HID + lane] = c2;
        g_h[(size_t)nd1 * HID + lane] = sigmoidf_(zo10) * tanhf(c2);
        float c3 = sf11 + sigmoidf_(zi11) * tanhf(zu11);
        g_c[(size_t)nd1 * HID + lane + 32] = c3;
        g_h[(size_t)nd1 * HID + lane + 32] = sigmoidf_(zo11) * tanhf(c3);
    }
    __syncwarp();
}

// ---------------- the mega-kernel ----------------
__global__ void __launch_bounds__(THREADS, 1)
mega_kernel(const float* __restrict__ A,
            const float* __restrict__ Wx_w,
            const float* __restrict__ Wx_b,
            const float* __restrict__ U_i, const float* __restrict__ U_f,
            const float* __restrict__ U_o, const float* __restrict__ U_u,
            const float* __restrict__ convW, const float* __restrict__ conv_b,
            float* __restrict__ out)
{
    extern __shared__ float sm[];
    __half* smh = (__half*)sm;
    const int tid  = threadIdx.x;
    const int lane = tid & 31;
    const int warp = tid >> 5;
    const int t0 = blockIdx.x * THREADS + tid;
    const int nt = TGRID * THREADS;

    // ========== phase 0: prep ==========
    for (int i = t0; i < NGEMM * INDIM / 4; i += nt) {
        float4 v = ((const float4*)Wx_w)[i];
        __half2 h0 = __floats2half2_rn(v.x, v.y);
        __half2 h1 = __floats2half2_rn(v.z, v.w);
        uint2 pk;
        pk.x = *(unsigned*)&h0; pk.y = *(unsigned*)&h1;
        ((uint2*)g_Bh)[i] = pk;
    }
    for (int idx = t0; idx < HID * HID; idx += nt) {
        int o = idx >> 6, h = idx & 63;
        g_Uit[h * HID + o] = U_i[idx];
        g_Uft[h * HID + o] = U_f[idx];
        g_Uot[h * HID + o] = U_o[idx];
        g_Uut[h * HID + o] = U_u[idx];
    }
    for (int idx = t0; idx < 2 * HID * HID; idx += nt) {
        int o = idx >> 7, kh = idx & 127;
        g_convWt[kh * HID + o] = convW[idx];
    }
    if (t0 < HID) {
        float vi = 0.f, vo = 0.f, vu = 0.f;
        for (int h = 0; h < HID; ++h) {
            float b = conv_b[h];
            vi += b * U_i[t0 * HID + h];
            vo += b * U_o[t0 * HID + h];
            vu += b * U_u[t0 * HID + h];
        }
        g_v[t0] = vi; g_v[HID + t0] = vo; g_v[2 * HID + t0] = vu;
    }
    gridbar(0);

    // ========== phase 1: fp16 GEMM with fused leaf epilogue ==========
    if (blockIdx.x < GBLOCKS) {
        const int m0 = (warp >> 2) * 32;
        const int n0 = (warp & 3) * 64;
        const int bm = blockIdx.x * BM;
        const int arow = tid >> 2;
        const int aq   = tid & 3;
        int agr = bm + arow; if (agr > NNODES - 1) agr = NNODES - 1;
        const float* agp = A + (size_t)agr * INDIM + aq * 8;

        const int rA = lane & 15;
        const int cA = (lane >> 4) * 8;
        const int rB = (lane & 7) + (lane >> 4) * 8;
        const int cB = ((lane >> 3) & 1) * 8;
        const unsigned sbase = (unsigned)__cvta_generic_to_shared(smh);
        const unsigned uA0 = ((m0 + rA) * PADH + cA) * 2;
        const unsigned uB0 = ((n0 + rB) * PADH + cB) * 2;

        float acc[2][8][4];
#pragma unroll
        for (int i = 0; i < 2; ++i)
#pragma unroll
            for (int j = 0; j < 8; ++j)
#pragma unroll
                for (int k = 0; k < 4; ++k) acc[i][j][k] = 0.f;

        float ar[8];
        auto ldgA = [&](int t) {
            const float4* p = (const float4*)(agp + t * BK);
            float4 u = p[0], v = p[1];
            ar[0] = u.x; ar[1] = u.y; ar[2] = u.z; ar[3] = u.w;
            ar[4] = v.x; ar[5] = v.y; ar[6] = v.z; ar[7] = v.w;
        };
        auto stsA = [&](int t) {
            __half2 p0 = __floats2half2_rn(ar[0], ar[1]);
            __half2 p1 = __floats2half2_rn(ar[2], ar[3]);
            __half2 p2 = __floats2half2_rn(ar[4], ar[5]);
            __half2 p3 = __floats2half2_rn(ar[6], ar[7]);
            uint4 pk;
            pk.x = *(unsigned*)&p0; pk.y = *(unsigned*)&p1;
            pk.z = *(unsigned*)&p2; pk.w = *(unsigned*)&p3;
            *(uint4*)(smh + (t & 1) * A_STH + arow * PADH + aq * 8) = pk;
        };
        auto issueB = [&](int t) {
            __half* stg = smh + B_BASEH + (t & 3) * B_STH;
            const int k0 = t * BK;
#pragma unroll
            for (int j = 0; j < 2; ++j) {
                int idx = tid + j * THREADS;
                int row = idx >> 2, c = idx & 3;
                cp_async16h(stg + row * PADH + c * 8,
                            g_Bh + (size_t)row * INDIM + k0 + c * 8);
            }
            cp_commit();
        };

        ldgA(0);
        issueB(0); issueB(1);

        for (int s = 0; s < NK; ++s) {
            stsA(s);
            if (s + 1 < NK) ldgA(s + 1);
            if (s + 2 < NK) issueB(s + 2); else cp_commit();
            asm volatile("cp.async.wait_group 2;" ::: "memory");
            __syncthreads();

            const unsigned stA = sbase + ((s & 1) * A_STH) * 2;
            const unsigned stB = sbase + (B_BASEH + (s & 3) * B_STH) * 2;

#pragma unroll
            for (int ks = 0; ks < 2; ++ks) {
                unsigned af[2][4], bf[8][2];
                ldsm_x4(af[0][0], af[0][1], af[0][2], af[0][3],
                        stA + uA0 + ks * 32);
                ldsm_x4(af[1][0], af[1][1], af[1][2], af[1][3],
                        stA + uA0 + 16 * PADH * 2 + ks * 32);
#pragma unroll
                for (int j = 0; j < 4; ++j)
                    ldsm_x4(bf[2 * j][0], bf[2 * j][1], bf[2 * j + 1][0], bf[2 * j + 1][1],
                            stB + uB0 + j * 16 * PADH * 2 + ks * 32);
#pragma unroll
                for (int im = 0; im < 2; ++im)
#pragma unroll
                    for (int in = 0; in < 8; ++in)
                        mma_f16(acc[im][in], af[im], bf[in]);
            }
        }

        // ---- epilogue: acc+bias -> smem buffer, leaf rows computed directly ----
        __syncthreads();
        float* swx = sm;
        const int gid = lane >> 2, tig = lane & 3;
#pragma unroll
        for (int im = 0; im < 2; ++im) {
#pragma unroll
            for (int in = 0; in < 8; ++in) {
                int r0 = m0 + im * 16 + gid;
                int cg = n0 + in * 8 + tig * 2;
                float b0 = Wx_b[cg], b1 = Wx_b[cg + 1];
                swx[r0 * 256 + cg]           = acc[im][in][0] + b0;
                swx[r0 * 256 + cg + 1]       = acc[im][in][1] + b1;
                swx[(r0 + 8) * 256 + cg]     = acc[im][in][2] + b0;
                swx[(r0 + 8) * 256 + cg + 1] = acc[im][in][3] + b1;
            }
        }
        __syncthreads();

#pragma unroll
        for (int k = 0; k < 16; ++k) {
            int idx = tid + k * THREADS;
            int row = idx >> 6, o = idx & 63;
            int node = bm + row;
            if (node < FIRST_LEAF) {
                float* dst = g_Wx + (size_t)node * NGEMM;
                const float* src = swx + row * 256;
                dst[o]       = src[o];
                dst[64 + o]  = src[64 + o];
                dst[128 + o] = src[128 + o];
                dst[192 + o] = src[192 + o];
            } else if (node < NNODES) {
                const float* src = swx + row * 256;
                float zi = src[o]       + g_v[o];
                float zo = src[128 + o] + g_v[64 + o];
                float zu = src[192 + o] + g_v[128 + o];
                float c = sigmoidf_(zi) * tanhf(zu);
                g_c[(size_t)node * HID + o] = c;
                g_h[(size_t)node * HID + o] = sigmoidf_(zo) * tanhf(c);
            }
        }
        __syncthreads();
    }

    // stage tree weights into smem
    for (int i = tid; i < 4096; i += THREADS) {
        sm[TS_UF + i] = g_Uft[i];
        sm[TS_UI + i] = g_Uit[i];
        sm[TS_UO + i] = g_Uot[i];
        sm[TS_UU + i] = g_Uut[i];
    }
    for (int i = tid; i < 8192; i += THREADS) sm[TS_CV + i] = g_convWt[i];
    gridbar(1);

    // ========== phase 2: subtrees d = 12..7, one subtree per block ==========
    float* shw = sm + TS_WB + warp * 640;
    float* scw = shw + 256;
    float* saw = shw + 512;
    const float cb0 = conv_b[lane], cb1 = conv_b[lane + 32];

    if (blockIdx.x < GBLOCKS) {
        const int r1 = 128 + blockIdx.x;       // subtree root index + 1
        for (int d = 12; d >= 7; --d) {
            const int n = 1 << (d - 7);        // 32,16,8,4,2,1
            const int start = (r1 << (d - 7)) - 1;
            if (n == 1) {
                if (warp == 0)
                    node_pair(start, start, false, lane,
                              sm + TS_UI, sm + TS_UF, sm + TS_UO, sm + TS_UU, sm + TS_CV,
                              shw, scw, saw, cb0, cb1, out);
            } else {
                for (int j = warp * 2; j < n; j += TWARPS * 2) {
                    node_pair(start + j, start + j + 1, true, lane,
                              sm + TS_UI, sm + TS_UF, sm + TS_UO, sm + TS_UU, sm + TS_CV,
                              shw, scw, saw, cb0, cb1, out);
                }
            }
            __syncthreads();
        }
    }

    // ========== merged tail barrier: blocks != 0 arrive & exit ==========
    __syncthreads();
    if (blockIdx.x != 0) {
        if (tid == 0) { __threadfence(); atomicAdd(&g_bar[2], 1u); }
        return;
    }
    if (tid == 0) {
        __threadfence();
        atomicAdd(&g_bar[2], 1u);
        while (*(volatile unsigned*)&g_bar[2] < (unsigned)TGRID) { __nanosleep(64); }
        __threadfence();
    }
    __syncthreads();

    // ========== phase 3: levels d = 6..0, block 0 only ==========
    for (int d = 6; d >= 0; --d) {
        const int n = 1 << d, start = n - 1;
        if (n == 1) {
            if (warp == 0)
                node_pair(0, 0, false, lane,
                          sm + TS_UI, sm + TS_UF, sm + TS_UO, sm + TS_UU, sm + TS_CV,
                          shw, scw, saw, cb0, cb1, out);
        } else {
            for (int j = warp * 2; j < n; j += TWARPS * 2) {
                node_pair(start + j, start + j + 1, true, lane,
                          sm + TS_UI, sm + TS_UF, sm + TS_UO, sm + TS_UU, sm + TS_CV,
                          shw, scw, saw, cb0, cb1, out);
            }
        }
        __syncthreads();
    }

    if (tid < 32) g_bar[tid] = 0;   // reset for graph replay (block 0 finishes last)
}

// ---------------- launch ----------------
extern "C" void kernel_launch(void* const* d_in, const int* in_sizes, int n_in,
                              void* d_out, int out_size)
{
    const float* inputs = (const float*)d_in[0];
    const float* Wx_w   = (const float*)d_in[1];
    const float* Wx_b   = (const float*)d_in[2];
    const float* U_i    = (const float*)d_in[3];
    const float* U_f    = (const float*)d_in[4];
    const float* U_o    = (const float*)d_in[5];
    const float* U_u    = (const float*)d_in[6];
    const float* convW  = (const float*)d_in[7];
    const float* conv_b = (const float*)d_in[8];
    float* out = (float*)d_out;

    cudaFuncSetAttribute(mega_kernel, cudaFuncAttributeMaxDynamicSharedMemorySize, SMEM_BYTES);
    mega_kernel<<<TGRID, THREADS, SMEM_BYTES>>>(inputs, Wx_w, Wx_b, U_i, U_f, U_o, U_u,
                                                convW, conv_b, out);
}